// round 2
// baseline (speedup 1.0000x reference)
#include <cuda_runtime.h>
#include <stdint.h>

// Problem constants (from reference setup_inputs)
#define N_NODES 50000
#define F_IN    256
#define F_HID   128
#define F_OUT   64
#define NEG_SLOPE 0.01f

// ---------------- scratch (static device globals; 16B-aligned for float4/red.v4)
__device__ __align__(16) float g_deg[N_NODES];
__device__ __align__(16) float g_deginv[N_NODES];
__device__ __align__(16) float g_h1[N_NODES * F_HID];   // x @ W1
__device__ __align__(16) float g_h[N_NODES * F_HID];    // agg1 -> leaky(agg1 + b1)
__device__ __align__(16) float g_agg2[N_NODES * F_HID]; // aggregation of g_h

// ---------------- degree ----------------------------------------------------
__global__ void deg_init_kernel(int n) {
    int i = blockIdx.x * blockDim.x + threadIdx.x;
    if (i < n) g_deg[i] = 1.0f;  // self-loop
}

__global__ void deg_count_kernel(const int* __restrict__ dst, int E) {
    int e = blockIdx.x * blockDim.x + threadIdx.x;
    if (e < E) atomicAdd(&g_deg[dst[e]], 1.0f);
}

__global__ void deg_fin_kernel(int n) {
    int i = blockIdx.x * blockDim.x + threadIdx.x;
    if (i < n) g_deginv[i] = rsqrtf(g_deg[i]);
}

// ---------------- SGEMM: C[M x 128] = A[M x K] * B[K x 128] -----------------
// 128x128 block tile, BK=8, 256 threads, 8x8 micro-tile per thread.
template <int K>
__global__ void __launch_bounds__(256)
sgemm128_kernel(const float* __restrict__ A, const float* __restrict__ B,
                float* __restrict__ C, int M) {
    __shared__ float As[8][128];
    __shared__ float Bs[8][128];

    const int tid = threadIdx.x;
    const int tx = tid & 15;   // 0..15 -> cols tx*8
    const int ty = tid >> 4;   // 0..15 -> rows ty*8
    const int block_row = blockIdx.x * 128;

    // A loading map: each thread loads one float4 along K
    const int arow = tid >> 1;          // 0..127
    const int akq  = (tid & 1) * 4;     // 0 or 4
    // B loading map: each thread loads one float4 (8 rows x 128 cols)
    const int bk = tid >> 5;            // 0..7
    const int bc = (tid & 31) * 4;      // 0..124

    float acc[8][8];
#pragma unroll
    for (int i = 0; i < 8; i++)
#pragma unroll
        for (int j = 0; j < 8; j++) acc[i][j] = 0.0f;

    for (int k0 = 0; k0 < K; k0 += 8) {
        // Load A tile (transposed into As[k][m])
        int grow = block_row + arow;
        float4 av = make_float4(0.f, 0.f, 0.f, 0.f);
        if (grow < M)
            av = *reinterpret_cast<const float4*>(A + (size_t)grow * K + k0 + akq);
        As[akq + 0][arow] = av.x;
        As[akq + 1][arow] = av.y;
        As[akq + 2][arow] = av.z;
        As[akq + 3][arow] = av.w;
        // Load B tile
        float4 bv = *reinterpret_cast<const float4*>(B + (size_t)(k0 + bk) * 128 + bc);
        *reinterpret_cast<float4*>(&Bs[bk][bc]) = bv;
        __syncthreads();

#pragma unroll
        for (int k = 0; k < 8; k++) {
            float a[8], b[8];
#pragma unroll
            for (int i = 0; i < 8; i++) a[i] = As[k][ty * 8 + i];
#pragma unroll
            for (int j = 0; j < 8; j++) b[j] = Bs[k][tx * 8 + j];
#pragma unroll
            for (int i = 0; i < 8; i++)
#pragma unroll
                for (int j = 0; j < 8; j++) acc[i][j] += a[i] * b[j];
        }
        __syncthreads();
    }

#pragma unroll
    for (int i = 0; i < 8; i++) {
        int row = block_row + ty * 8 + i;
        if (row < M) {
            float4 v0 = make_float4(acc[i][0], acc[i][1], acc[i][2], acc[i][3]);
            float4 v1 = make_float4(acc[i][4], acc[i][5], acc[i][6], acc[i][7]);
            *reinterpret_cast<float4*>(C + (size_t)row * 128 + tx * 8)     = v0;
            *reinterpret_cast<float4*>(C + (size_t)row * 128 + tx * 8 + 4) = v1;
        }
    }
}

// ---------------- GEMM2: out = agg2 @ [W_mu | W_logvar] + [b_mu | b_logvar] -
__global__ void __launch_bounds__(256)
gemm2_kernel(const float* __restrict__ A,
             const float* __restrict__ Wmu, const float* __restrict__ Wlv,
             const float* __restrict__ bmu, const float* __restrict__ blv,
             float* __restrict__ out, int M) {
    __shared__ float As[8][128];
    __shared__ float Bs[8][128];

    const int tid = threadIdx.x;
    const int tx = tid & 15;
    const int ty = tid >> 4;
    const int block_row = blockIdx.x * 128;

    const int arow = tid >> 1;
    const int akq  = (tid & 1) * 4;
    const int bk = tid >> 5;
    const int bc = (tid & 31) * 4;

    float acc[8][8];
#pragma unroll
    for (int i = 0; i < 8; i++)
#pragma unroll
        for (int j = 0; j < 8; j++) acc[i][j] = 0.0f;

    const int K = 128;
    for (int k0 = 0; k0 < K; k0 += 8) {
        int grow = block_row + arow;
        float4 av = make_float4(0.f, 0.f, 0.f, 0.f);
        if (grow < M)
            av = *reinterpret_cast<const float4*>(A + (size_t)grow * K + k0 + akq);
        As[akq + 0][arow] = av.x;
        As[akq + 1][arow] = av.y;
        As[akq + 2][arow] = av.z;
        As[akq + 3][arow] = av.w;

        float4 bv;
        if (bc < 64)
            bv = *reinterpret_cast<const float4*>(Wmu + (size_t)(k0 + bk) * 64 + bc);
        else
            bv = *reinterpret_cast<const float4*>(Wlv + (size_t)(k0 + bk) * 64 + (bc - 64));
        *reinterpret_cast<float4*>(&Bs[bk][bc]) = bv;
        __syncthreads();

#pragma unroll
        for (int k = 0; k < 8; k++) {
            float a[8], b[8];
#pragma unroll
            for (int i = 0; i < 8; i++) a[i] = As[k][ty * 8 + i];
#pragma unroll
            for (int j = 0; j < 8; j++) b[j] = Bs[k][tx * 8 + j];
#pragma unroll
            for (int i = 0; i < 8; i++)
#pragma unroll
                for (int j = 0; j < 8; j++) acc[i][j] += a[i] * b[j];
        }
        __syncthreads();
    }

    // epilogue: bias + split mu/logvar (8 consecutive cols stay in one half)
    const int colbase = tx * 8;
    const bool is_mu = (colbase < 64);
    const float* bias = is_mu ? bmu : blv;
    const int c0 = is_mu ? colbase : colbase - 64;
    float bb[8];
#pragma unroll
    for (int j = 0; j < 8; j++) bb[j] = bias[c0 + j];
    float* base = is_mu ? out : (out + (size_t)M * 64);

#pragma unroll
    for (int i = 0; i < 8; i++) {
        int row = block_row + ty * 8 + i;
        if (row < M) {
            float4 v0 = make_float4(acc[i][0] + bb[0], acc[i][1] + bb[1],
                                    acc[i][2] + bb[2], acc[i][3] + bb[3]);
            float4 v1 = make_float4(acc[i][4] + bb[4], acc[i][5] + bb[5],
                                    acc[i][6] + bb[6], acc[i][7] + bb[7]);
            *reinterpret_cast<float4*>(base + (size_t)row * 64 + c0)     = v0;
            *reinterpret_cast<float4*>(base + (size_t)row * 64 + c0 + 4) = v1;
        }
    }
}

// ---------------- self-loop init: dst = deginv[node]^2 * src ----------------
__global__ void self_init_kernel(const float* __restrict__ src,
                                 float* __restrict__ dst, int n_nodes) {
    int i4 = blockIdx.x * blockDim.x + threadIdx.x;  // over n_nodes*32 float4s
    int total4 = n_nodes * (F_HID / 4);
    if (i4 >= total4) return;
    int node = i4 >> 5;  // F_HID/4 = 32 float4 per node
    float di = g_deginv[node];
    float s = di * di;
    float4 v = reinterpret_cast<const float4*>(src)[i4];
    v.x *= s; v.y *= s; v.z *= s; v.w *= s;
    reinterpret_cast<float4*>(dst)[i4] = v;
}

// ---------------- edge scatter: agg[dst] += norm * h[src] -------------------
// One warp per edge; each lane handles one float4 (32*4 = 128 features).
__global__ void __launch_bounds__(256)
scatter_kernel(const float* __restrict__ h, float* __restrict__ agg,
               const int* __restrict__ src, const int* __restrict__ dst,
               int E) {
    int warp = (blockIdx.x * blockDim.x + threadIdx.x) >> 5;
    int lane = threadIdx.x & 31;
    if (warp >= E) return;
    int s = __ldg(&src[warp]);
    int d = __ldg(&dst[warp]);
    float norm = __ldg(&g_deginv[s]) * __ldg(&g_deginv[d]);
    float4 v = __ldg(reinterpret_cast<const float4*>(h + (size_t)s * F_HID) + lane);
    float* p = agg + (size_t)d * F_HID + lane * 4;
    asm volatile("red.global.add.v4.f32 [%0], {%1, %2, %3, %4};"
                 :: "l"(p), "f"(v.x * norm), "f"(v.y * norm),
                    "f"(v.z * norm), "f"(v.w * norm)
                 : "memory");
}

// ---------------- bias + LeakyReLU in place ---------------------------------
__global__ void bias_leaky_kernel(float* __restrict__ buf,
                                  const float* __restrict__ b1, int n_nodes) {
    int i = blockIdx.x * blockDim.x + threadIdx.x;
    int total = n_nodes * F_HID;
    if (i >= total) return;
    int f = i & (F_HID - 1);
    float v = buf[i] + __ldg(&b1[f]);
    buf[i] = (v > 0.0f) ? v : v * NEG_SLOPE;
}

// ---------------- launch ----------------------------------------------------
extern "C" void kernel_launch(void* const* d_in, const int* in_sizes, int n_in,
                              void* d_out, int out_size) {
    const float* x    = (const float*)d_in[0];
    const int*   ei   = (const int*)d_in[1];   // jnp.int64 degrades to int32 (x64 off)
    const float* W1   = (const float*)d_in[2];
    const float* b1   = (const float*)d_in[3];
    const float* Wmu  = (const float*)d_in[4];
    const float* bmu  = (const float*)d_in[5];
    const float* Wlv  = (const float*)d_in[6];
    const float* blv  = (const float*)d_in[7];
    float* out = (float*)d_out;

    const int N = in_sizes[0] / F_IN;       // 50000
    const int E = in_sizes[1] / 2;          // 800000
    const int* src = ei;
    const int* dst = ei + E;

    float *h1, *h, *agg2;
    cudaGetSymbolAddress((void**)&h1,   g_h1);
    cudaGetSymbolAddress((void**)&h,    g_h);
    cudaGetSymbolAddress((void**)&agg2, g_agg2);

    // 1) degrees
    deg_init_kernel<<<(N + 255) / 256, 256>>>(N);
    deg_count_kernel<<<(E + 255) / 256, 256>>>(dst, E);
    deg_fin_kernel<<<(N + 255) / 256, 256>>>(N);

    // 2) GEMM1: h1 = x @ W1
    sgemm128_kernel<F_IN><<<(N + 127) / 128, 256>>>(x, W1, h1, N);

    // 3) layer-1 aggregation into g_h (self-loop init + edge scatter)
    int total4 = N * (F_HID / 4);
    self_init_kernel<<<(total4 + 255) / 256, 256>>>(h1, h, N);
    scatter_kernel<<<(E * 32 + 255) / 256, 256>>>(h1, h, src, dst, E);

    // 4) bias + leaky in place
    bias_leaky_kernel<<<(N * F_HID + 255) / 256, 256>>>(h, b1, N);

    // 5) layer-2 aggregation of h into agg2 (aggregate-then-transform:
    //    segment_sum(norm*(h@W)[src]) == segment_sum(norm*h[src]) @ W)
    self_init_kernel<<<(total4 + 255) / 256, 256>>>(h, agg2, N);
    scatter_kernel<<<(E * 32 + 255) / 256, 256>>>(h, agg2, src, dst, E);

    // 6) GEMM2 with bias + mu/logvar split into d_out
    gemm2_kernel<<<(N + 127) / 128, 256>>>(agg2, Wmu, Wlv, bmu, blv, out, N);
}

// round 3
// speedup vs baseline: 1.0960x; 1.0960x over previous
#include <cuda_runtime.h>
#include <stdint.h>

#define N_NODES 50000
#define F_IN    256
#define F_HID   128
#define F_OUT   64
#define NEG_SLOPE 0.01f

// ---------------- scratch (static device globals; 16B-aligned) --------------
__device__ __align__(16) float g_deg[N_NODES];
__device__ __align__(16) float g_deginv[N_NODES];
__device__ __align__(16) float g_h1[N_NODES * F_HID];   // x @ W1
__device__ __align__(16) float g_h[N_NODES * F_HID];    // agg1 -> leaky(agg1 + b1)
__device__ __align__(16) float g_agg2[N_NODES * F_HID]; // aggregation of g_h

// ---------------- degree ----------------------------------------------------
__global__ void deg_init_kernel(int n) {
    int i = blockIdx.x * blockDim.x + threadIdx.x;
    if (i < n) g_deg[i] = 1.0f;  // self-loop
}

__global__ void deg_count_kernel(const int* __restrict__ dst, int E) {
    int e = blockIdx.x * blockDim.x + threadIdx.x;
    if (e < E) atomicAdd(&g_deg[dst[e]], 1.0f);
}

__global__ void deg_fin_kernel(int n) {
    int i = blockIdx.x * blockDim.x + threadIdx.x;
    if (i < n) g_deginv[i] = rsqrtf(g_deg[i]);
}

// ---------------- double-buffered SGEMM mainloop (macro-shared) --------------
// C[M x 128] = A[M x K] * B[K x 128]; 128x128 tile, BK=8, 256 thr, 8x8 microtile.

// GEMM1 with fused self-loop init: C = A@B, C2 = C * deginv[row]^2
template <int K>
__global__ void __launch_bounds__(256)
sgemm1_kernel(const float* __restrict__ A, const float* __restrict__ B,
              float* __restrict__ C, float* __restrict__ C2, int M) {
    __shared__ float As[2][8][128];
    __shared__ float Bs[2][8][128];

    const int tid = threadIdx.x;
    const int tx = tid & 15;
    const int ty = tid >> 4;
    const int block_row = blockIdx.x * 128;

    const int arow = tid >> 1;
    const int akq  = (tid & 1) * 4;
    const int bk = tid >> 5;
    const int bc = (tid & 31) * 4;
    const int grow = block_row + arow;
    const bool avalid = (grow < M);

    float acc[8][8];
#pragma unroll
    for (int i = 0; i < 8; i++)
#pragma unroll
        for (int j = 0; j < 8; j++) acc[i][j] = 0.0f;

    // preload tile 0
    float4 av = avalid ? *reinterpret_cast<const float4*>(A + (size_t)grow * K + akq)
                       : make_float4(0.f, 0.f, 0.f, 0.f);
    float4 bv = *reinterpret_cast<const float4*>(B + (size_t)bk * 128 + bc);
    As[0][akq + 0][arow] = av.x; As[0][akq + 1][arow] = av.y;
    As[0][akq + 2][arow] = av.z; As[0][akq + 3][arow] = av.w;
    *reinterpret_cast<float4*>(&Bs[0][bk][bc]) = bv;
    __syncthreads();

    const int NT = K / 8;
    int p = 0;
#pragma unroll 4
    for (int t = 0; t < NT; t++) {
        if (t + 1 < NT) {
            int k0 = (t + 1) * 8;
            av = avalid ? *reinterpret_cast<const float4*>(A + (size_t)grow * K + k0 + akq)
                        : make_float4(0.f, 0.f, 0.f, 0.f);
            bv = *reinterpret_cast<const float4*>(B + (size_t)(k0 + bk) * 128 + bc);
        }
#pragma unroll
        for (int k = 0; k < 8; k++) {
            float4 a0 = *reinterpret_cast<const float4*>(&As[p][k][ty * 8]);
            float4 a1 = *reinterpret_cast<const float4*>(&As[p][k][ty * 8 + 4]);
            float4 b0 = *reinterpret_cast<const float4*>(&Bs[p][k][tx * 8]);
            float4 b1 = *reinterpret_cast<const float4*>(&Bs[p][k][tx * 8 + 4]);
            float a[8] = {a0.x, a0.y, a0.z, a0.w, a1.x, a1.y, a1.z, a1.w};
            float b[8] = {b0.x, b0.y, b0.z, b0.w, b1.x, b1.y, b1.z, b1.w};
#pragma unroll
            for (int i = 0; i < 8; i++)
#pragma unroll
                for (int j = 0; j < 8; j++) acc[i][j] += a[i] * b[j];
        }
        if (t + 1 < NT) {
            int q = p ^ 1;
            As[q][akq + 0][arow] = av.x; As[q][akq + 1][arow] = av.y;
            As[q][akq + 2][arow] = av.z; As[q][akq + 3][arow] = av.w;
            *reinterpret_cast<float4*>(&Bs[q][bk][bc]) = bv;
            __syncthreads();
            p = q;
        }
    }

#pragma unroll
    for (int i = 0; i < 8; i++) {
        int row = block_row + ty * 8 + i;
        if (row < M) {
            float di = g_deginv[row];
            float s = di * di;
            float4 v0 = make_float4(acc[i][0], acc[i][1], acc[i][2], acc[i][3]);
            float4 v1 = make_float4(acc[i][4], acc[i][5], acc[i][6], acc[i][7]);
            *reinterpret_cast<float4*>(C + (size_t)row * 128 + tx * 8)     = v0;
            *reinterpret_cast<float4*>(C + (size_t)row * 128 + tx * 8 + 4) = v1;
            float4 w0 = make_float4(v0.x * s, v0.y * s, v0.z * s, v0.w * s);
            float4 w1 = make_float4(v1.x * s, v1.y * s, v1.z * s, v1.w * s);
            *reinterpret_cast<float4*>(C2 + (size_t)row * 128 + tx * 8)     = w0;
            *reinterpret_cast<float4*>(C2 + (size_t)row * 128 + tx * 8 + 4) = w1;
        }
    }
}

// GEMM2: out = A @ [W_mu | W_logvar] + [b_mu | b_logvar], split outputs.
__global__ void __launch_bounds__(256)
gemm2_kernel(const float* __restrict__ A,
             const float* __restrict__ Wmu, const float* __restrict__ Wlv,
             const float* __restrict__ bmu, const float* __restrict__ blv,
             float* __restrict__ out, int M) {
    __shared__ float As[2][8][128];
    __shared__ float Bs[2][8][128];

    const int tid = threadIdx.x;
    const int tx = tid & 15;
    const int ty = tid >> 4;
    const int block_row = blockIdx.x * 128;

    const int arow = tid >> 1;
    const int akq  = (tid & 1) * 4;
    const int bk = tid >> 5;
    const int bc = (tid & 31) * 4;
    const int grow = block_row + arow;
    const bool avalid = (grow < M);
    const int K = 128;

    float acc[8][8];
#pragma unroll
    for (int i = 0; i < 8; i++)
#pragma unroll
        for (int j = 0; j < 8; j++) acc[i][j] = 0.0f;

    auto ldgB = [&](int k0) -> float4 {
        if (bc < 64)
            return *reinterpret_cast<const float4*>(Wmu + (size_t)(k0 + bk) * 64 + bc);
        return *reinterpret_cast<const float4*>(Wlv + (size_t)(k0 + bk) * 64 + (bc - 64));
    };

    float4 av = avalid ? *reinterpret_cast<const float4*>(A + (size_t)grow * K + akq)
                       : make_float4(0.f, 0.f, 0.f, 0.f);
    float4 bv = ldgB(0);
    As[0][akq + 0][arow] = av.x; As[0][akq + 1][arow] = av.y;
    As[0][akq + 2][arow] = av.z; As[0][akq + 3][arow] = av.w;
    *reinterpret_cast<float4*>(&Bs[0][bk][bc]) = bv;
    __syncthreads();

    const int NT = K / 8;
    int p = 0;
#pragma unroll 4
    for (int t = 0; t < NT; t++) {
        if (t + 1 < NT) {
            int k0 = (t + 1) * 8;
            av = avalid ? *reinterpret_cast<const float4*>(A + (size_t)grow * K + k0 + akq)
                        : make_float4(0.f, 0.f, 0.f, 0.f);
            bv = ldgB(k0);
        }
#pragma unroll
        for (int k = 0; k < 8; k++) {
            float4 a0 = *reinterpret_cast<const float4*>(&As[p][k][ty * 8]);
            float4 a1 = *reinterpret_cast<const float4*>(&As[p][k][ty * 8 + 4]);
            float4 b0 = *reinterpret_cast<const float4*>(&Bs[p][k][tx * 8]);
            float4 b1 = *reinterpret_cast<const float4*>(&Bs[p][k][tx * 8 + 4]);
            float a[8] = {a0.x, a0.y, a0.z, a0.w, a1.x, a1.y, a1.z, a1.w};
            float b[8] = {b0.x, b0.y, b0.z, b0.w, b1.x, b1.y, b1.z, b1.w};
#pragma unroll
            for (int i = 0; i < 8; i++)
#pragma unroll
                for (int j = 0; j < 8; j++) acc[i][j] += a[i] * b[j];
        }
        if (t + 1 < NT) {
            int q = p ^ 1;
            As[q][akq + 0][arow] = av.x; As[q][akq + 1][arow] = av.y;
            As[q][akq + 2][arow] = av.z; As[q][akq + 3][arow] = av.w;
            *reinterpret_cast<float4*>(&Bs[q][bk][bc]) = bv;
            __syncthreads();
            p = q;
        }
    }

    const int colbase = tx * 8;
    const bool is_mu = (colbase < 64);
    const float* bias = is_mu ? bmu : blv;
    const int c0 = is_mu ? colbase : colbase - 64;
    float bb[8];
#pragma unroll
    for (int j = 0; j < 8; j++) bb[j] = bias[c0 + j];
    float* base = is_mu ? out : (out + (size_t)M * 64);

#pragma unroll
    for (int i = 0; i < 8; i++) {
        int row = block_row + ty * 8 + i;
        if (row < M) {
            float4 v0 = make_float4(acc[i][0] + bb[0], acc[i][1] + bb[1],
                                    acc[i][2] + bb[2], acc[i][3] + bb[3]);
            float4 v1 = make_float4(acc[i][4] + bb[4], acc[i][5] + bb[5],
                                    acc[i][6] + bb[6], acc[i][7] + bb[7]);
            *reinterpret_cast<float4*>(base + (size_t)row * 64 + c0)     = v0;
            *reinterpret_cast<float4*>(base + (size_t)row * 64 + c0 + 4) = v1;
        }
    }
}

// ---------------- edge scatter: agg[dst] += norm * h[src] -------------------
__global__ void __launch_bounds__(256)
scatter_kernel(const float* __restrict__ h, float* __restrict__ agg,
               const int* __restrict__ src, const int* __restrict__ dst,
               int E) {
    int warp = (blockIdx.x * blockDim.x + threadIdx.x) >> 5;
    int lane = threadIdx.x & 31;
    if (warp >= E) return;
    int s = __ldg(&src[warp]);
    int d = __ldg(&dst[warp]);
    float norm = __ldg(&g_deginv[s]) * __ldg(&g_deginv[d]);
    float4 v = __ldg(reinterpret_cast<const float4*>(h + (size_t)s * F_HID) + lane);
    float* p = agg + (size_t)d * F_HID + lane * 4;
    asm volatile("red.global.add.v4.f32 [%0], {%1, %2, %3, %4};"
                 :: "l"(p), "f"(v.x * norm), "f"(v.y * norm),
                    "f"(v.z * norm), "f"(v.w * norm)
                 : "memory");
}

// ------- fused: h = leaky(agg1 + b1); agg2 = h * deginv^2 (self-loop init) --
__global__ void bias_leaky_selfinit_kernel(float* __restrict__ h,
                                           float* __restrict__ agg2,
                                           const float* __restrict__ b1,
                                           int n_nodes) {
    int i4 = blockIdx.x * blockDim.x + threadIdx.x;
    int total4 = n_nodes * (F_HID / 4);
    if (i4 >= total4) return;
    int node = i4 >> 5;
    int f4 = i4 & 31;
    float di = g_deginv[node];
    float s = di * di;
    float4 v = reinterpret_cast<const float4*>(h)[i4];
    float4 b = reinterpret_cast<const float4*>(b1)[f4];
    v.x += b.x; v.y += b.y; v.z += b.z; v.w += b.w;
    v.x = (v.x > 0.f) ? v.x : v.x * NEG_SLOPE;
    v.y = (v.y > 0.f) ? v.y : v.y * NEG_SLOPE;
    v.z = (v.z > 0.f) ? v.z : v.z * NEG_SLOPE;
    v.w = (v.w > 0.f) ? v.w : v.w * NEG_SLOPE;
    reinterpret_cast<float4*>(h)[i4] = v;
    float4 w = make_float4(v.x * s, v.y * s, v.z * s, v.w * s);
    reinterpret_cast<float4*>(agg2)[i4] = w;
}

// ---------------- launch ----------------------------------------------------
extern "C" void kernel_launch(void* const* d_in, const int* in_sizes, int n_in,
                              void* d_out, int out_size) {
    const float* x    = (const float*)d_in[0];
    const int*   ei   = (const int*)d_in[1];   // int32 (JAX x64 disabled)
    const float* W1   = (const float*)d_in[2];
    const float* b1   = (const float*)d_in[3];
    const float* Wmu  = (const float*)d_in[4];
    const float* bmu  = (const float*)d_in[5];
    const float* Wlv  = (const float*)d_in[6];
    const float* blv  = (const float*)d_in[7];
    float* out = (float*)d_out;

    const int N = in_sizes[0] / F_IN;       // 50000
    const int E = in_sizes[1] / 2;          // 800000
    const int* src = ei;
    const int* dst = ei + E;

    float *h1, *h, *agg2;
    cudaGetSymbolAddress((void**)&h1,   g_h1);
    cudaGetSymbolAddress((void**)&h,    g_h);
    cudaGetSymbolAddress((void**)&agg2, g_agg2);

    // 1) degrees
    deg_init_kernel<<<(N + 255) / 256, 256>>>(N);
    deg_count_kernel<<<(E + 255) / 256, 256>>>(dst, E);
    deg_fin_kernel<<<(N + 255) / 256, 256>>>(N);

    // 2) GEMM1: h1 = x@W1; h = h1 * deginv^2 (fused self-loop init)
    sgemm1_kernel<F_IN><<<(N + 127) / 128, 256>>>(x, W1, h1, h, N);

    // 3) layer-1 edge scatter into h
    scatter_kernel<<<((size_t)E * 32 + 255) / 256, 256>>>(h1, h, src, dst, E);

    // 4) h = leaky(h + b1); agg2 = h * deginv^2 (fused)
    int total4 = N * (F_HID / 4);
    bias_leaky_selfinit_kernel<<<(total4 + 255) / 256, 256>>>(h, agg2, b1, N);

    // 5) layer-2 edge scatter into agg2
    scatter_kernel<<<((size_t)E * 32 + 255) / 256, 256>>>(h, agg2, src, dst, E);

    // 6) GEMM2 with bias + mu/logvar split into d_out
    gemm2_kernel<<<(N + 127) / 128, 256>>>(agg2, Wmu, Wlv, bmu, blv, out, N);
}

// round 5
// speedup vs baseline: 1.3448x; 1.2271x over previous
#include <cuda_runtime.h>
#include <cuda_bf16.h>
#include <stdint.h>

#define N_NODES 50000
#define F_IN    256
#define F_HID   128
#define NEG_SLOPE 0.01f

typedef __nv_bfloat16 bf16;

// ---------------- scratch ------------------------------------------------------
__device__ __align__(16) float g_deg[N_NODES];
__device__ __align__(16) float g_deginv[N_NODES];
__device__ __align__(16) bf16  g_xs[(size_t)N_NODES * 512];   // x rows: [hi(256)|lo(256)]
__device__ __align__(16) bf16  g_w1s[2 * 256 * 128];          // [hi|lo] of W1, [k][n]
__device__ __align__(16) bf16  g_h2s[(size_t)N_NODES * 256];  // scaled acc2: [hi(128)|lo(128)]
__device__ __align__(16) bf16  g_w2s[2 * 128 * 128];          // [hi|lo] of [Wmu|Wlv], [k][n]
__device__ __align__(16) float g_hs[N_NODES * F_HID];         // gather source (pre-scaled)
__device__ __align__(16) float g_acc1[N_NODES * F_HID];
__device__ __align__(16) float g_acc2[N_NODES * F_HID];

// ---------------- PTX helpers ---------------------------------------------------
__device__ __forceinline__ uint32_t smem_u32(const void* p) {
    uint32_t a;
    asm("{ .reg .u64 t; cvta.to.shared.u64 t, %1; cvt.u32.u64 %0, t; }" : "=r"(a) : "l"(p));
    return a;
}
#define CP16(dst, src) \
    asm volatile("cp.async.cg.shared.global [%0], [%1], 16;" :: "r"(dst), "l"(src))
#define CP_COMMIT() asm volatile("cp.async.commit_group;")
#define CP_WAIT1()  asm volatile("cp.async.wait_group 1;")
#define CP_WAIT0()  asm volatile("cp.async.wait_group 0;")

__device__ __forceinline__ void ldsm_x4(uint32_t& r0, uint32_t& r1, uint32_t& r2,
                                        uint32_t& r3, uint32_t addr) {
    asm volatile("ldmatrix.sync.aligned.m8n8.x4.shared.b16 {%0,%1,%2,%3}, [%4];"
                 : "=r"(r0), "=r"(r1), "=r"(r2), "=r"(r3) : "r"(addr));
}
__device__ __forceinline__ void ldsm_x4t(uint32_t& r0, uint32_t& r1, uint32_t& r2,
                                         uint32_t& r3, uint32_t addr) {
    asm volatile("ldmatrix.sync.aligned.m8n8.x4.trans.shared.b16 {%0,%1,%2,%3}, [%4];"
                 : "=r"(r0), "=r"(r1), "=r"(r2), "=r"(r3) : "r"(addr));
}
__device__ __forceinline__ void mma16816(float* c, uint32_t a0, uint32_t a1, uint32_t a2,
                                         uint32_t a3, uint32_t b0, uint32_t b1) {
    asm volatile("mma.sync.aligned.m16n8k16.row.col.f32.bf16.bf16.f32 "
                 "{%0,%1,%2,%3}, {%4,%5,%6,%7}, {%8,%9}, {%0,%1,%2,%3};"
                 : "+f"(c[0]), "+f"(c[1]), "+f"(c[2]), "+f"(c[3])
                 : "r"(a0), "r"(a1), "r"(a2), "r"(a3), "r"(b0), "r"(b1));
}

// ---------------- degree --------------------------------------------------------
__global__ void deg_init_kernel(int n) {
    int i = blockIdx.x * blockDim.x + threadIdx.x;
    if (i < n) g_deg[i] = 1.0f;
}
__global__ void deg_count_kernel(const int* __restrict__ dst, int E) {
    int e = blockIdx.x * blockDim.x + threadIdx.x;
    if (e < E) atomicAdd(&g_deg[dst[e]], 1.0f);
}
__global__ void deg_fin_kernel(int n) {
    int i = blockIdx.x * blockDim.x + threadIdx.x;
    if (i < n) g_deginv[i] = rsqrtf(g_deg[i]);
}

// ---------------- conversions ---------------------------------------------------
__global__ void split_x_kernel(const float* __restrict__ x, int M) {
    int i4 = blockIdx.x * blockDim.x + threadIdx.x;  // M*64 float4s
    if (i4 >= M * (F_IN / 4)) return;
    int row = i4 >> 6, c4 = i4 & 63;
    float4 v = reinterpret_cast<const float4*>(x)[i4];
    bf16* o = g_xs + (size_t)row * 512 + c4 * 4;
    bf16 h0 = __float2bfloat16(v.x), h1 = __float2bfloat16(v.y);
    bf16 h2 = __float2bfloat16(v.z), h3 = __float2bfloat16(v.w);
    o[0] = h0; o[1] = h1; o[2] = h2; o[3] = h3;
    o[256] = __float2bfloat16(v.x - __bfloat162float(h0));
    o[257] = __float2bfloat16(v.y - __bfloat162float(h1));
    o[258] = __float2bfloat16(v.z - __bfloat162float(h2));
    o[259] = __float2bfloat16(v.w - __bfloat162float(h3));
}
__global__ void build_w1_kernel(const float* __restrict__ W1) {
    int i = blockIdx.x * blockDim.x + threadIdx.x;  // 256*128
    if (i >= 256 * 128) return;
    float w = W1[i];
    bf16 hi = __float2bfloat16(w);
    g_w1s[i] = hi;
    g_w1s[256 * 128 + i] = __float2bfloat16(w - __bfloat162float(hi));
}
__global__ void build_w2_kernel(const float* __restrict__ Wmu, const float* __restrict__ Wlv) {
    int i = blockIdx.x * blockDim.x + threadIdx.x;  // 128*128
    if (i >= 128 * 128) return;
    int k = i >> 7, n = i & 127;
    float w = (n < 64) ? Wmu[k * 64 + n] : Wlv[k * 64 + (n - 64)];
    bf16 hi = __float2bfloat16(w);
    g_w2s[i] = hi;
    g_w2s[128 * 128 + i] = __float2bfloat16(w - __bfloat162float(hi));
}
// acc2 -> scaled bf16 hi/lo
__global__ void split_h2_kernel(const float* __restrict__ acc2, int M) {
    int i4 = blockIdx.x * blockDim.x + threadIdx.x;  // M*32 float4s
    if (i4 >= M * (F_HID / 4)) return;
    int row = i4 >> 5, c4 = i4 & 31;
    float d = g_deginv[row];
    float4 v = reinterpret_cast<const float4*>(acc2)[i4];
    v.x *= d; v.y *= d; v.z *= d; v.w *= d;
    bf16* o = g_h2s + (size_t)row * 256 + c4 * 4;
    bf16 h0 = __float2bfloat16(v.x), h1 = __float2bfloat16(v.y);
    bf16 h2 = __float2bfloat16(v.z), h3 = __float2bfloat16(v.w);
    o[0] = h0; o[1] = h1; o[2] = h2; o[3] = h3;
    o[128] = __float2bfloat16(v.x - __bfloat162float(h0));
    o[129] = __float2bfloat16(v.y - __bfloat162float(h1));
    o[130] = __float2bfloat16(v.z - __bfloat162float(h2));
    o[131] = __float2bfloat16(v.w - __bfloat162float(h3));
}

// ---------------- MMA GEMM core -------------------------------------------------
// Block 128x128, BK=32, 8 warps (4 m x 2 n), warp tile 32x64.
// smem pitches: A 40 bf16 (80B), B 136 bf16 (272B) -> conflict-free ldmatrix.
struct SmemT {
    bf16 As[2][128 * 40];
    bf16 Bs[2][32 * 136];
};
#define A_BUF_BYTES (128 * 40 * 2)
#define B_BUF_BYTES (32 * 136 * 2)

// Runs the 3-pass split mainloop. Abase: bf16 matrix with row stride `astride`;
// pass 0: (A hi @ B hi), pass 1: (A hi @ B lo), pass 2: (A lo @ B hi).
// A lo offset = kcols; B lo offset = kcols*128. kcols = K per pass (256 or 128).
template <int KCOLS>
__device__ __forceinline__ void mma_mainloop(
    SmemT& sm, const bf16* __restrict__ Abase, int astride,
    const bf16* __restrict__ Bbase, int M, int block_row,
    float c[2][8][4]) {
    const int tid = threadIdx.x;
    const int lane = tid & 31, wid = tid >> 5;
    const int warp_m = wid & 3, warp_n = wid >> 2;

    // global->smem load mapping
    const int ar = tid >> 2, aseg = tid & 3;            // A: rows ar, ar+64; 16B seg
    const int bk = tid >> 4, bseg = tid & 15;           // B: rows bk, bk+16; 16B seg
    const int g0 = min(block_row + ar, M - 1);
    const int g1 = min(block_row + ar + 64, M - 1);
    const bf16* ap0 = Abase + (size_t)g0 * astride + aseg * 8;
    const bf16* ap1 = Abase + (size_t)g1 * astride + aseg * 8;
    const uint32_t asm0 = smem_u32(&sm.As[0][ar * 40 + aseg * 8]);
    const uint32_t asm1 = smem_u32(&sm.As[0][(ar + 64) * 40 + aseg * 8]);
    const uint32_t bsm0 = smem_u32(&sm.Bs[0][bk * 136 + bseg * 8]);
    const uint32_t bsm1 = smem_u32(&sm.Bs[0][(bk + 16) * 136 + bseg * 8]);

    const int IPP = KCOLS / 32;       // iters per pass
    const int NT = 3 * IPP;

    // ldmatrix base offsets (per thread)
    const uint32_t a_ld0 = smem_u32(&sm.As[0][0]);
    const uint32_t b_ld0 = smem_u32(&sm.Bs[0][0]);

#define ISSUE(it, buf) do { \
        int _pass = (it) / IPP, _kk = ((it) % IPP) * 32; \
        int _aoff = (_pass == 2) ? KCOLS : 0; \
        const bf16* _bb = Bbase + ((_pass == 1) ? (size_t)KCOLS * 128 : 0); \
        CP16(asm0 + (buf) * A_BUF_BYTES, ap0 + _aoff + _kk); \
        CP16(asm1 + (buf) * A_BUF_BYTES, ap1 + _aoff + _kk); \
        CP16(bsm0 + (buf) * B_BUF_BYTES, _bb + (size_t)(_kk + bk) * 128 + bseg * 8); \
        CP16(bsm1 + (buf) * B_BUF_BYTES, _bb + (size_t)(_kk + bk + 16) * 128 + bseg * 8); \
        CP_COMMIT(); \
    } while (0)

    ISSUE(0, 0);
#pragma unroll 1
    for (int it = 0; it < NT; it++) {
        const int p = it & 1;
        if (it + 1 < NT) { ISSUE(it + 1, p ^ 1); CP_WAIT1(); }
        else            { CP_WAIT0(); }
        __syncthreads();

        const uint32_t abase = a_ld0 + p * A_BUF_BYTES;
        const uint32_t bbase = b_ld0 + p * B_BUF_BYTES;
#pragma unroll
        for (int ks = 0; ks < 2; ks++) {
            uint32_t a[2][4];
#pragma unroll
            for (int mt = 0; mt < 2; mt++) {
                int row = warp_m * 32 + mt * 16 + (lane & 15);
                int col = ks * 16 + (lane >> 4) * 8;
                ldsm_x4(a[mt][0], a[mt][1], a[mt][2], a[mt][3],
                        abase + (row * 40 + col) * 2);
            }
            uint32_t b[4][4];
#pragma unroll
            for (int np = 0; np < 4; np++) {
                int row = ks * 16 + (lane & 7) + ((lane >> 3) & 1) * 8;
                int col = warp_n * 64 + np * 16 + (lane >> 4) * 8;
                ldsm_x4t(b[np][0], b[np][1], b[np][2], b[np][3],
                         bbase + (row * 136 + col) * 2);
            }
#pragma unroll
            for (int mt = 0; mt < 2; mt++)
#pragma unroll
                for (int nt = 0; nt < 8; nt++)
                    mma16816(c[mt][nt], a[mt][0], a[mt][1], a[mt][2], a[mt][3],
                             b[nt >> 1][(nt & 1) * 2], b[nt >> 1][(nt & 1) * 2 + 1]);
        }
        __syncthreads();
    }
#undef ISSUE
}

// GEMM1: C = x@W1 (split); epilogue v = C*deginv[row] -> hs and acc1.
__global__ void __launch_bounds__(256)
mma_gemm1_kernel(float* __restrict__ hs, float* __restrict__ acc1, int M) {
    __shared__ SmemT sm;
    const int lane = threadIdx.x & 31, wid = threadIdx.x >> 5;
    const int warp_m = wid & 3, warp_n = wid >> 2;
    const int block_row = blockIdx.x * 128;

    float c[2][8][4];
#pragma unroll
    for (int i = 0; i < 2; i++)
#pragma unroll
        for (int j = 0; j < 8; j++)
#pragma unroll
            for (int q = 0; q < 4; q++) c[i][j][q] = 0.0f;

    mma_mainloop<256>(sm, g_xs, 512, g_w1s, M, block_row, c);

#pragma unroll
    for (int mt = 0; mt < 2; mt++) {
        int row0 = block_row + warp_m * 32 + mt * 16 + (lane >> 2);
        int row1 = row0 + 8;
        float s0 = (row0 < M) ? __ldg(&g_deginv[row0]) : 0.0f;
        float s1 = (row1 < M) ? __ldg(&g_deginv[row1]) : 0.0f;
#pragma unroll
        for (int nt = 0; nt < 8; nt++) {
            int col = warp_n * 64 + nt * 8 + (lane & 3) * 2;
            if (row0 < M) {
                float2 v = make_float2(c[mt][nt][0] * s0, c[mt][nt][1] * s0);
                *reinterpret_cast<float2*>(hs + (size_t)row0 * 128 + col) = v;
                *reinterpret_cast<float2*>(acc1 + (size_t)row0 * 128 + col) = v;
            }
            if (row1 < M) {
                float2 v = make_float2(c[mt][nt][2] * s1, c[mt][nt][3] * s1);
                *reinterpret_cast<float2*>(hs + (size_t)row1 * 128 + col) = v;
                *reinterpret_cast<float2*>(acc1 + (size_t)row1 * 128 + col) = v;
            }
        }
    }
}

// GEMM2: C = h2s@[Wmu|Wlv] (split); epilogue += bias, split mu/logvar into out.
__global__ void __launch_bounds__(256)
mma_gemm2_kernel(const float* __restrict__ bmu, const float* __restrict__ blv,
                 float* __restrict__ out, int M) {
    __shared__ SmemT sm;
    const int lane = threadIdx.x & 31, wid = threadIdx.x >> 5;
    const int warp_m = wid & 3, warp_n = wid >> 2;
    const int block_row = blockIdx.x * 128;

    float c[2][8][4];
#pragma unroll
    for (int i = 0; i < 2; i++)
#pragma unroll
        for (int j = 0; j < 8; j++)
#pragma unroll
            for (int q = 0; q < 4; q++) c[i][j][q] = 0.0f;

    mma_mainloop<128>(sm, g_h2s, 256, g_w2s, M, block_row, c);

    // warp_n = 0 -> mu (cols 0..63), warp_n = 1 -> logvar (cols 64..127)
    const float* bias = warp_n ? blv : bmu;
    float* base = out + (warp_n ? (size_t)M * 64 : 0);
#pragma unroll
    for (int mt = 0; mt < 2; mt++) {
        int row0 = block_row + warp_m * 32 + mt * 16 + (lane >> 2);
        int row1 = row0 + 8;
#pragma unroll
        for (int nt = 0; nt < 8; nt++) {
            int col = nt * 8 + (lane & 3) * 2;  // 0..63 within half
            float b0 = __ldg(&bias[col]), b1 = __ldg(&bias[col + 1]);
            if (row0 < M)
                *reinterpret_cast<float2*>(base + (size_t)row0 * 64 + col) =
                    make_float2(c[mt][nt][0] + b0, c[mt][nt][1] + b1);
            if (row1 < M)
                *reinterpret_cast<float2*>(base + (size_t)row1 * 64 + col) =
                    make_float2(c[mt][nt][2] + b0, c[mt][nt][3] + b1);
        }
    }
}

// ---------------- edge scatter: acc[dst] += hs[src] (rows pre-scaled) -----------
__global__ void __launch_bounds__(256)
scatter_kernel(const float* __restrict__ hs, float* __restrict__ acc,
               const int* __restrict__ src, const int* __restrict__ dst, int E) {
    int e = (blockIdx.x * blockDim.x + threadIdx.x) >> 5;
    int lane = threadIdx.x & 31;
    if (e >= E) return;
    int s = __ldg(&src[e]);
    int d = __ldg(&dst[e]);
    float4 v = __ldg(reinterpret_cast<const float4*>(hs + (size_t)s * F_HID) + lane);
    float* p = acc + (size_t)d * F_HID + lane * 4;
    asm volatile("red.global.add.v4.f32 [%0], {%1, %2, %3, %4};"
                 :: "l"(p), "f"(v.x), "f"(v.y), "f"(v.z), "f"(v.w) : "memory");
}

// ------ fused: v = leaky(deginv*acc1 + b1); w = v*deginv -> hs and acc2 ---------
__global__ void bias_leaky_kernel(const float* __restrict__ acc1,
                                  float* __restrict__ hs, float* __restrict__ acc2,
                                  const float* __restrict__ b1, int n_nodes) {
    int i4 = blockIdx.x * blockDim.x + threadIdx.x;
    int total4 = n_nodes * (F_HID / 4);
    if (i4 >= total4) return;
    int node = i4 >> 5, f4 = i4 & 31;
    float di = g_deginv[node];
    float4 v = reinterpret_cast<const float4*>(acc1)[i4];
    float4 b = reinterpret_cast<const float4*>(b1)[f4];
    v.x = v.x * di + b.x; v.y = v.y * di + b.y;
    v.z = v.z * di + b.z; v.w = v.w * di + b.w;
    v.x = (v.x > 0.f) ? v.x : v.x * NEG_SLOPE;
    v.y = (v.y > 0.f) ? v.y : v.y * NEG_SLOPE;
    v.z = (v.z > 0.f) ? v.z : v.z * NEG_SLOPE;
    v.w = (v.w > 0.f) ? v.w : v.w * NEG_SLOPE;
    float4 w = make_float4(v.x * di, v.y * di, v.z * di, v.w * di);
    reinterpret_cast<float4*>(hs)[i4] = w;
    reinterpret_cast<float4*>(acc2)[i4] = w;
}

// ---------------- launch ---------------------------------------------------------
extern "C" void kernel_launch(void* const* d_in, const int* in_sizes, int n_in,
                              void* d_out, int out_size) {
    const float* x   = (const float*)d_in[0];
    const int*   ei  = (const int*)d_in[1];   // int32 (JAX x64 disabled)
    const float* W1  = (const float*)d_in[2];
    const float* b1  = (const float*)d_in[3];
    const float* Wmu = (const float*)d_in[4];
    const float* bmu = (const float*)d_in[5];
    const float* Wlv = (const float*)d_in[6];
    const float* blv = (const float*)d_in[7];
    float* out = (float*)d_out;

    const int N = in_sizes[0] / F_IN;  // 50000
    const int E = in_sizes[1] / 2;     // 800000
    const int* src = ei;
    const int* dst = ei + E;

    float *hs, *acc1, *acc2;
    cudaGetSymbolAddress((void**)&hs,   g_hs);
    cudaGetSymbolAddress((void**)&acc1, g_acc1);
    cudaGetSymbolAddress((void**)&acc2, g_acc2);

    // 1) degrees
    deg_init_kernel<<<(N + 255) / 256, 256>>>(N);
    deg_count_kernel<<<(E + 255) / 256, 256>>>(dst, E);
    deg_fin_kernel<<<(N + 255) / 256, 256>>>(N);

    // 2) bf16 conversions
    split_x_kernel<<<(N * (F_IN / 4) + 255) / 256, 256>>>(x, N);
    build_w1_kernel<<<(256 * 128 + 255) / 256, 256>>>(W1);
    build_w2_kernel<<<(128 * 128 + 255) / 256, 256>>>(Wmu, Wlv);

    // 3) MMA GEMM1: hs = acc1 = (x@W1) * deginv[row]
    mma_gemm1_kernel<<<(N + 127) / 128, 256>>>(hs, acc1, N);

    // 4) layer-1 scatter
    scatter_kernel<<<((size_t)E * 32 + 255) / 256, 256>>>(hs, acc1, src, dst, E);

    // 5) bias + leaky + self-loop init for layer 2
    int total4 = N * (F_HID / 4);
    bias_leaky_kernel<<<(total4 + 255) / 256, 256>>>(acc1, hs, acc2, b1, N);

    // 6) layer-2 scatter
    scatter_kernel<<<((size_t)E * 32 + 255) / 256, 256>>>(hs, acc2, src, dst, E);

    // 7) split acc2 (scaled) to bf16 hi/lo, then MMA GEMM2 into out
    split_h2_kernel<<<(total4 + 255) / 256, 256>>>(acc2, N);
    mma_gemm2_kernel<<<(N + 127) / 128, 256>>>(bmu, blv, out, N);
}

// round 6
// speedup vs baseline: 2.2602x; 1.6807x over previous
#include <cuda_runtime.h>
#include <cuda_bf16.h>
#include <stdint.h>

#define N_NODES 50000
#define F_IN    256
#define F_HID   128
#define NEG_SLOPE 0.01f
#define MAXE    800000
#define SCAN_B  256

typedef __nv_bfloat16 bf16;

// ---------------- scratch ------------------------------------------------------
__device__ __align__(16) int   g_hist[N_NODES];
__device__ __align__(16) int   g_off[N_NODES + 1];
__device__ __align__(16) int   g_cursor[N_NODES];
__device__ __align__(16) int   g_bsums[(N_NODES + SCAN_B - 1) / SCAN_B];
__device__ __align__(16) int   g_esrc[MAXE];
__device__ __align__(16) float g_deginv[N_NODES];
__device__ __align__(16) bf16  g_xs[(size_t)N_NODES * 512];   // x rows: [hi(256)|lo(256)]
__device__ __align__(16) bf16  g_w1s[2 * 256 * 128];          // [hi|lo] of W1, [k][n]
__device__ __align__(16) bf16  g_h2s[(size_t)N_NODES * 256];  // scaled agg2: [hi(128)|lo(128)]
__device__ __align__(16) bf16  g_w2s[2 * 128 * 128];          // [hi|lo] of [Wmu|Wlv], [k][n]
__device__ __align__(16) float g_hs1[N_NODES * F_HID];        // layer-1 gather source
__device__ __align__(16) float g_hs2[N_NODES * F_HID];        // layer-2 gather source

// ---------------- PTX helpers ---------------------------------------------------
__device__ __forceinline__ uint32_t smem_u32(const void* p) {
    uint32_t a;
    asm("{ .reg .u64 t; cvta.to.shared.u64 t, %1; cvt.u32.u64 %0, t; }" : "=r"(a) : "l"(p));
    return a;
}
#define CP16(dst, src) \
    asm volatile("cp.async.cg.shared.global [%0], [%1], 16;" :: "r"(dst), "l"(src))
#define CP_COMMIT() asm volatile("cp.async.commit_group;")
#define CP_WAIT1()  asm volatile("cp.async.wait_group 1;")
#define CP_WAIT0()  asm volatile("cp.async.wait_group 0;")

__device__ __forceinline__ void ldsm_x4(uint32_t& r0, uint32_t& r1, uint32_t& r2,
                                        uint32_t& r3, uint32_t addr) {
    asm volatile("ldmatrix.sync.aligned.m8n8.x4.shared.b16 {%0,%1,%2,%3}, [%4];"
                 : "=r"(r0), "=r"(r1), "=r"(r2), "=r"(r3) : "r"(addr));
}
__device__ __forceinline__ void ldsm_x4t(uint32_t& r0, uint32_t& r1, uint32_t& r2,
                                         uint32_t& r3, uint32_t addr) {
    asm volatile("ldmatrix.sync.aligned.m8n8.x4.trans.shared.b16 {%0,%1,%2,%3}, [%4];"
                 : "=r"(r0), "=r"(r1), "=r"(r2), "=r"(r3) : "r"(addr));
}
__device__ __forceinline__ void mma16816(float* c, uint32_t a0, uint32_t a1, uint32_t a2,
                                         uint32_t a3, uint32_t b0, uint32_t b1) {
    asm volatile("mma.sync.aligned.m16n8k16.row.col.f32.bf16.bf16.f32 "
                 "{%0,%1,%2,%3}, {%4,%5,%6,%7}, {%8,%9}, {%0,%1,%2,%3};"
                 : "+f"(c[0]), "+f"(c[1]), "+f"(c[2]), "+f"(c[3])
                 : "r"(a0), "r"(a1), "r"(a2), "r"(a3), "r"(b0), "r"(b1));
}

// ---------------- CSR build ------------------------------------------------------
__global__ void hist_init_kernel(int n) {
    int i = blockIdx.x * blockDim.x + threadIdx.x;
    if (i < n) g_hist[i] = 0;
}
__global__ void hist_kernel(const int* __restrict__ dst, int E) {
    int e = blockIdx.x * blockDim.x + threadIdx.x;
    if (e < E) atomicAdd(&g_hist[dst[e]], 1);
}
__global__ void deg_fin_kernel(int n) {
    int i = blockIdx.x * blockDim.x + threadIdx.x;
    if (i < n) g_deginv[i] = rsqrtf(1.0f + (float)g_hist[i]);
}

__device__ __forceinline__ int block_exscan(int v, int tid, int* total) {
    __shared__ int wsum[8];
    int lane = tid & 31, w = tid >> 5;
    int x = v;
#pragma unroll
    for (int o = 1; o < 32; o <<= 1) {
        int t = __shfl_up_sync(0xFFFFFFFFu, x, o);
        if (lane >= o) x += t;
    }
    if (lane == 31) wsum[w] = x;
    __syncthreads();
    if (w == 0) {
        int s = (lane < 8) ? wsum[lane] : 0;
#pragma unroll
        for (int o = 1; o < 8; o <<= 1) {
            int t = __shfl_up_sync(0xFFFFFFFFu, s, o);
            if (lane >= o) s += t;
        }
        if (lane < 8) wsum[lane] = s;
    }
    __syncthreads();
    int woff = (w == 0) ? 0 : wsum[w - 1];
    *total = wsum[7];
    return woff + x - v;
}

__global__ void scanA_kernel(int n) {
    int i = blockIdx.x * SCAN_B + threadIdx.x;
    int v = (i < n) ? g_hist[i] : 0;
    int tot;
    int ex = block_exscan(v, threadIdx.x, &tot);
    if (i < n) g_off[i] = ex;
    if (threadIdx.x == 0) g_bsums[blockIdx.x] = tot;
}
__global__ void scanB_kernel(int nb) {
    int tid = threadIdx.x;
    int v = (tid < nb) ? g_bsums[tid] : 0;
    int tot;
    int ex = block_exscan(v, tid, &tot);
    if (tid < nb) g_bsums[tid] = ex;
}
__global__ void scanC_kernel(int n, int E) {
    int i = blockIdx.x * SCAN_B + threadIdx.x;
    if (i < n) {
        int o = g_off[i] + g_bsums[blockIdx.x];
        g_off[i] = o;
        g_cursor[i] = o;
    }
    if (i == 0) g_off[n] = E;
}
__global__ void place_kernel(const int* __restrict__ src, const int* __restrict__ dst, int E) {
    int e = blockIdx.x * blockDim.x + threadIdx.x;
    if (e >= E) return;
    int pos = atomicAdd(&g_cursor[dst[e]], 1);
    g_esrc[pos] = src[e];
}

// ---------------- conversions ---------------------------------------------------
__global__ void split_x_kernel(const float* __restrict__ x, int M) {
    int i4 = blockIdx.x * blockDim.x + threadIdx.x;  // M*64 float4s
    if (i4 >= M * (F_IN / 4)) return;
    int row = i4 >> 6, c4 = i4 & 63;
    float4 v = reinterpret_cast<const float4*>(x)[i4];
    bf16* o = g_xs + (size_t)row * 512 + c4 * 4;
    bf16 h0 = __float2bfloat16(v.x), h1 = __float2bfloat16(v.y);
    bf16 h2 = __float2bfloat16(v.z), h3 = __float2bfloat16(v.w);
    o[0] = h0; o[1] = h1; o[2] = h2; o[3] = h3;
    o[256] = __float2bfloat16(v.x - __bfloat162float(h0));
    o[257] = __float2bfloat16(v.y - __bfloat162float(h1));
    o[258] = __float2bfloat16(v.z - __bfloat162float(h2));
    o[259] = __float2bfloat16(v.w - __bfloat162float(h3));
}
__global__ void build_w1_kernel(const float* __restrict__ W1) {
    int i = blockIdx.x * blockDim.x + threadIdx.x;  // 256*128
    if (i >= 256 * 128) return;
    float w = W1[i];
    bf16 hi = __float2bfloat16(w);
    g_w1s[i] = hi;
    g_w1s[256 * 128 + i] = __float2bfloat16(w - __bfloat162float(hi));
}
__global__ void build_w2_kernel(const float* __restrict__ Wmu, const float* __restrict__ Wlv) {
    int i = blockIdx.x * blockDim.x + threadIdx.x;  // 128*128
    if (i >= 128 * 128) return;
    int k = i >> 7, n = i & 127;
    float w = (n < 64) ? Wmu[k * 64 + n] : Wlv[k * 64 + (n - 64)];
    bf16 hi = __float2bfloat16(w);
    g_w2s[i] = hi;
    g_w2s[128 * 128 + i] = __float2bfloat16(w - __bfloat162float(hi));
}

// ---------------- MMA GEMM core (128x128 blk, BK=32, 8 warps, 32x64 warp tile) ---
struct SmemT {
    bf16 As[2][128 * 40];
    bf16 Bs[2][32 * 136];
};
#define A_BUF_BYTES (128 * 40 * 2)
#define B_BUF_BYTES (32 * 136 * 2)

template <int KCOLS>
__device__ __forceinline__ void mma_mainloop(
    SmemT& sm, const bf16* __restrict__ Abase, int astride,
    const bf16* __restrict__ Bbase, int M, int block_row,
    float c[2][8][4]) {
    const int tid = threadIdx.x;
    const int lane = tid & 31, wid = tid >> 5;
    const int warp_m = wid & 3, warp_n = wid >> 2;

    const int ar = tid >> 2, aseg = tid & 3;
    const int bk = tid >> 4, bseg = tid & 15;
    const int g0 = min(block_row + ar, M - 1);
    const int g1 = min(block_row + ar + 64, M - 1);
    const bf16* ap0 = Abase + (size_t)g0 * astride + aseg * 8;
    const bf16* ap1 = Abase + (size_t)g1 * astride + aseg * 8;
    const uint32_t asm0 = smem_u32(&sm.As[0][ar * 40 + aseg * 8]);
    const uint32_t asm1 = smem_u32(&sm.As[0][(ar + 64) * 40 + aseg * 8]);
    const uint32_t bsm0 = smem_u32(&sm.Bs[0][bk * 136 + bseg * 8]);
    const uint32_t bsm1 = smem_u32(&sm.Bs[0][(bk + 16) * 136 + bseg * 8]);

    const int IPP = KCOLS / 32;
    const int NT = 3 * IPP;
    const uint32_t a_ld0 = smem_u32(&sm.As[0][0]);
    const uint32_t b_ld0 = smem_u32(&sm.Bs[0][0]);

#define ISSUE(it, buf) do { \
        int _pass = (it) / IPP, _kk = ((it) % IPP) * 32; \
        int _aoff = (_pass == 2) ? KCOLS : 0; \
        const bf16* _bb = Bbase + ((_pass == 1) ? (size_t)KCOLS * 128 : 0); \
        CP16(asm0 + (buf) * A_BUF_BYTES, ap0 + _aoff + _kk); \
        CP16(asm1 + (buf) * A_BUF_BYTES, ap1 + _aoff + _kk); \
        CP16(bsm0 + (buf) * B_BUF_BYTES, _bb + (size_t)(_kk + bk) * 128 + bseg * 8); \
        CP16(bsm1 + (buf) * B_BUF_BYTES, _bb + (size_t)(_kk + bk + 16) * 128 + bseg * 8); \
        CP_COMMIT(); \
    } while (0)

    ISSUE(0, 0);
#pragma unroll 1
    for (int it = 0; it < NT; it++) {
        const int p = it & 1;
        if (it + 1 < NT) { ISSUE(it + 1, p ^ 1); CP_WAIT1(); }
        else            { CP_WAIT0(); }
        __syncthreads();

        const uint32_t abase = a_ld0 + p * A_BUF_BYTES;
        const uint32_t bbase = b_ld0 + p * B_BUF_BYTES;
#pragma unroll
        for (int ks = 0; ks < 2; ks++) {
            uint32_t a[2][4];
#pragma unroll
            for (int mt = 0; mt < 2; mt++) {
                int row = warp_m * 32 + mt * 16 + (lane & 15);
                int col = ks * 16 + (lane >> 4) * 8;
                ldsm_x4(a[mt][0], a[mt][1], a[mt][2], a[mt][3],
                        abase + (row * 40 + col) * 2);
            }
            uint32_t b[4][4];
#pragma unroll
            for (int np = 0; np < 4; np++) {
                int row = ks * 16 + (lane & 7) + ((lane >> 3) & 1) * 8;
                int col = warp_n * 64 + np * 16 + (lane >> 4) * 8;
                ldsm_x4t(b[np][0], b[np][1], b[np][2], b[np][3],
                         bbase + (row * 136 + col) * 2);
            }
#pragma unroll
            for (int mt = 0; mt < 2; mt++)
#pragma unroll
                for (int nt = 0; nt < 8; nt++)
                    mma16816(c[mt][nt], a[mt][0], a[mt][1], a[mt][2], a[mt][3],
                             b[nt >> 1][(nt & 1) * 2], b[nt >> 1][(nt & 1) * 2 + 1]);
        }
        __syncthreads();
    }
#undef ISSUE
}

// GEMM1: hs1 = (x@W1) * deginv[row]
__global__ void __launch_bounds__(256)
mma_gemm1_kernel(float* __restrict__ hs1, int M) {
    __shared__ SmemT sm;
    const int lane = threadIdx.x & 31, wid = threadIdx.x >> 5;
    const int warp_m = wid & 3, warp_n = wid >> 2;
    const int block_row = blockIdx.x * 128;

    float c[2][8][4];
#pragma unroll
    for (int i = 0; i < 2; i++)
#pragma unroll
        for (int j = 0; j < 8; j++)
#pragma unroll
            for (int q = 0; q < 4; q++) c[i][j][q] = 0.0f;

    mma_mainloop<256>(sm, g_xs, 512, g_w1s, M, block_row, c);

#pragma unroll
    for (int mt = 0; mt < 2; mt++) {
        int row0 = block_row + warp_m * 32 + mt * 16 + (lane >> 2);
        int row1 = row0 + 8;
        float s0 = (row0 < M) ? __ldg(&g_deginv[row0]) : 0.0f;
        float s1 = (row1 < M) ? __ldg(&g_deginv[row1]) : 0.0f;
#pragma unroll
        for (int nt = 0; nt < 8; nt++) {
            int col = warp_n * 64 + nt * 8 + (lane & 3) * 2;
            if (row0 < M)
                *reinterpret_cast<float2*>(hs1 + (size_t)row0 * 128 + col) =
                    make_float2(c[mt][nt][0] * s0, c[mt][nt][1] * s0);
            if (row1 < M)
                *reinterpret_cast<float2*>(hs1 + (size_t)row1 * 128 + col) =
                    make_float2(c[mt][nt][2] * s1, c[mt][nt][3] * s1);
        }
    }
}

// GEMM2: out = h2s @ [Wmu|Wlv] + bias, split mu/logvar
__global__ void __launch_bounds__(256)
mma_gemm2_kernel(const float* __restrict__ bmu, const float* __restrict__ blv,
                 float* __restrict__ out, int M) {
    __shared__ SmemT sm;
    const int lane = threadIdx.x & 31, wid = threadIdx.x >> 5;
    const int warp_m = wid & 3, warp_n = wid >> 2;
    const int block_row = blockIdx.x * 128;

    float c[2][8][4];
#pragma unroll
    for (int i = 0; i < 2; i++)
#pragma unroll
        for (int j = 0; j < 8; j++)
#pragma unroll
            for (int q = 0; q < 4; q++) c[i][j][q] = 0.0f;

    mma_mainloop<128>(sm, g_h2s, 256, g_w2s, M, block_row, c);

    const float* bias = warp_n ? blv : bmu;
    float* base = out + (warp_n ? (size_t)M * 64 : 0);
#pragma unroll
    for (int mt = 0; mt < 2; mt++) {
        int row0 = block_row + warp_m * 32 + mt * 16 + (lane >> 2);
        int row1 = row0 + 8;
#pragma unroll
        for (int nt = 0; nt < 8; nt++) {
            int col = nt * 8 + (lane & 3) * 2;
            float b0 = __ldg(&bias[col]), b1 = __ldg(&bias[col + 1]);
            if (row0 < M)
                *reinterpret_cast<float2*>(base + (size_t)row0 * 64 + col) =
                    make_float2(c[mt][nt][0] + b0, c[mt][nt][1] + b1);
            if (row1 < M)
                *reinterpret_cast<float2*>(base + (size_t)row1 * 64 + col) =
                    make_float2(c[mt][nt][2] + b0, c[mt][nt][3] + b1);
        }
    }
}

// --------- agg1: warp/node; acc = hs1[d] + sum(hs1[src]); h = leaky(di*acc+b1);
//           hs2 = h*di ------------------------------------------------------------
__global__ void __launch_bounds__(256)
agg1_kernel(const float* __restrict__ hs1, const float* __restrict__ b1,
            float* __restrict__ hs2, int N) {
    int node = (blockIdx.x * blockDim.x + threadIdx.x) >> 5;
    int lane = threadIdx.x & 31;
    if (node >= N) return;
    int beg = g_off[node], end = g_off[node + 1];
    float4 acc = __ldg(reinterpret_cast<const float4*>(hs1 + (size_t)node * 128) + lane);
    int j = beg;
    for (; j + 3 < end; j += 4) {
        int s0 = __ldg(&g_esrc[j]),     s1 = __ldg(&g_esrc[j + 1]);
        int s2 = __ldg(&g_esrc[j + 2]), s3 = __ldg(&g_esrc[j + 3]);
        float4 v0 = __ldg(reinterpret_cast<const float4*>(hs1 + (size_t)s0 * 128) + lane);
        float4 v1 = __ldg(reinterpret_cast<const float4*>(hs1 + (size_t)s1 * 128) + lane);
        float4 v2 = __ldg(reinterpret_cast<const float4*>(hs1 + (size_t)s2 * 128) + lane);
        float4 v3 = __ldg(reinterpret_cast<const float4*>(hs1 + (size_t)s3 * 128) + lane);
        acc.x += v0.x + v1.x + v2.x + v3.x;
        acc.y += v0.y + v1.y + v2.y + v3.y;
        acc.z += v0.z + v1.z + v2.z + v3.z;
        acc.w += v0.w + v1.w + v2.w + v3.w;
    }
    for (; j < end; j++) {
        int s = __ldg(&g_esrc[j]);
        float4 v = __ldg(reinterpret_cast<const float4*>(hs1 + (size_t)s * 128) + lane);
        acc.x += v.x; acc.y += v.y; acc.z += v.z; acc.w += v.w;
    }
    float di = __ldg(&g_deginv[node]);
    float4 b = __ldg(reinterpret_cast<const float4*>(b1) + lane);
    float4 v;
    v.x = acc.x * di + b.x; v.y = acc.y * di + b.y;
    v.z = acc.z * di + b.z; v.w = acc.w * di + b.w;
    v.x = (v.x > 0.f) ? v.x : v.x * NEG_SLOPE;
    v.y = (v.y > 0.f) ? v.y : v.y * NEG_SLOPE;
    v.z = (v.z > 0.f) ? v.z : v.z * NEG_SLOPE;
    v.w = (v.w > 0.f) ? v.w : v.w * NEG_SLOPE;
    float4 w = make_float4(v.x * di, v.y * di, v.z * di, v.w * di);
    *(reinterpret_cast<float4*>(hs2 + (size_t)node * 128) + lane) = w;
}

// --------- agg2: warp/node; w = di*(hs2[d]+sum(hs2[src])); h2s = bf16 split(w) ----
__global__ void __launch_bounds__(256)
agg2_kernel(const float* __restrict__ hs2, int N) {
    int node = (blockIdx.x * blockDim.x + threadIdx.x) >> 5;
    int lane = threadIdx.x & 31;
    if (node >= N) return;
    int beg = g_off[node], end = g_off[node + 1];
    float4 acc = __ldg(reinterpret_cast<const float4*>(hs2 + (size_t)node * 128) + lane);
    int j = beg;
    for (; j + 3 < end; j += 4) {
        int s0 = __ldg(&g_esrc[j]),     s1 = __ldg(&g_esrc[j + 1]);
        int s2 = __ldg(&g_esrc[j + 2]), s3 = __ldg(&g_esrc[j + 3]);
        float4 v0 = __ldg(reinterpret_cast<const float4*>(hs2 + (size_t)s0 * 128) + lane);
        float4 v1 = __ldg(reinterpret_cast<const float4*>(hs2 + (size_t)s1 * 128) + lane);
        float4 v2 = __ldg(reinterpret_cast<const float4*>(hs2 + (size_t)s2 * 128) + lane);
        float4 v3 = __ldg(reinterpret_cast<const float4*>(hs2 + (size_t)s3 * 128) + lane);
        acc.x += v0.x + v1.x + v2.x + v3.x;
        acc.y += v0.y + v1.y + v2.y + v3.y;
        acc.z += v0.z + v1.z + v2.z + v3.z;
        acc.w += v0.w + v1.w + v2.w + v3.w;
    }
    for (; j < end; j++) {
        int s = __ldg(&g_esrc[j]);
        float4 v = __ldg(reinterpret_cast<const float4*>(hs2 + (size_t)s * 128) + lane);
        acc.x += v.x; acc.y += v.y; acc.z += v.z; acc.w += v.w;
    }
    float di = __ldg(&g_deginv[node]);
    float4 w = make_float4(acc.x * di, acc.y * di, acc.z * di, acc.w * di);
    bf16 h0 = __float2bfloat16(w.x), h1 = __float2bfloat16(w.y);
    bf16 h2 = __float2bfloat16(w.z), h3 = __float2bfloat16(w.w);
    bf16 l0 = __float2bfloat16(w.x - __bfloat162float(h0));
    bf16 l1 = __float2bfloat16(w.y - __bfloat162float(h1));
    bf16 l2 = __float2bfloat16(w.z - __bfloat162float(h2));
    bf16 l3 = __float2bfloat16(w.w - __bfloat162float(h3));
    bf16* o = g_h2s + (size_t)node * 256 + lane * 4;
    o[0] = h0; o[1] = h1; o[2] = h2; o[3] = h3;
    o[128] = l0; o[129] = l1; o[130] = l2; o[131] = l3;
}

// ---------------- launch ---------------------------------------------------------
extern "C" void kernel_launch(void* const* d_in, const int* in_sizes, int n_in,
                              void* d_out, int out_size) {
    const float* x   = (const float*)d_in[0];
    const int*   ei  = (const int*)d_in[1];   // int32 (JAX x64 disabled)
    const float* W1  = (const float*)d_in[2];
    const float* b1  = (const float*)d_in[3];
    const float* Wmu = (const float*)d_in[4];
    const float* bmu = (const float*)d_in[5];
    const float* Wlv = (const float*)d_in[6];
    const float* blv = (const float*)d_in[7];
    float* out = (float*)d_out;

    const int N = in_sizes[0] / F_IN;  // 50000
    const int E = in_sizes[1] / 2;     // 800000
    const int* src = ei;
    const int* dst = ei + E;

    float *hs1, *hs2;
    cudaGetSymbolAddress((void**)&hs1, g_hs1);
    cudaGetSymbolAddress((void**)&hs2, g_hs2);

    const int nScanBlocks = (N + SCAN_B - 1) / SCAN_B;

    // 1) CSR build: histogram -> scan -> place; degrees
    hist_init_kernel<<<(N + 255) / 256, 256>>>(N);
    hist_kernel<<<(E + 255) / 256, 256>>>(dst, E);
    deg_fin_kernel<<<(N + 255) / 256, 256>>>(N);
    scanA_kernel<<<nScanBlocks, SCAN_B>>>(N);
    scanB_kernel<<<1, SCAN_B>>>(nScanBlocks);
    scanC_kernel<<<nScanBlocks, SCAN_B>>>(N, E);
    place_kernel<<<(E + 255) / 256, 256>>>(src, dst, E);

    // 2) bf16 conversions (overlap-friendly; independent of CSR)
    split_x_kernel<<<(N * (F_IN / 4) + 255) / 256, 256>>>(x, N);
    build_w1_kernel<<<(256 * 128 + 255) / 256, 256>>>(W1);
    build_w2_kernel<<<(128 * 128 + 255) / 256, 256>>>(Wmu, Wlv);

    // 3) MMA GEMM1: hs1 = (x@W1) * deginv[row]
    mma_gemm1_kernel<<<(N + 127) / 128, 256>>>(hs1, N);

    // 4) agg1 (CSR gather + self + bias + leaky + rescale) -> hs2
    agg1_kernel<<<(N * 32 + 255) / 256, 256>>>(hs1, b1, hs2, N);

    // 5) agg2 (CSR gather + self + scale + bf16 split) -> g_h2s
    agg2_kernel<<<(N * 32 + 255) / 256, 256>>>(hs2, N);

    // 6) MMA GEMM2 + bias + mu/logvar split
    mma_gemm2_kernel<<<(N + 127) / 128, 256>>>(bmu, blv, out, N);
}

// round 7
// speedup vs baseline: 2.5665x; 1.1355x over previous
#include <cuda_runtime.h>
#include <cuda_bf16.h>
#include <cuda_fp16.h>
#include <stdint.h>

#define N_NODES 50000
#define F_IN    256
#define F_HID   128
#define NEG_SLOPE 0.01f
#define MAXE    800000
#define SCAN_B  256

typedef __nv_bfloat16 bf16;

// ---------------- scratch ------------------------------------------------------
__device__ __align__(16) int    g_hist[N_NODES];
__device__ __align__(16) int    g_off[N_NODES + 1];
__device__ __align__(16) int    g_cursor[N_NODES];
__device__ __align__(16) int    g_bsums[(N_NODES + SCAN_B - 1) / SCAN_B];
__device__ __align__(16) int    g_esrc[MAXE];
__device__ __align__(16) float  g_deginv[N_NODES];
__device__ __align__(16) bf16   g_w1s[2 * 256 * 128];           // [hi|lo] of W1, [k][n]
__device__ __align__(16) bf16   g_h2s[(size_t)N_NODES * 256];   // agg2 out: [hi(128)|lo(128)]
__device__ __align__(16) bf16   g_w2s[2 * 128 * 128];           // [hi|lo] of [Wmu|Wlv], [k][n]
__device__ __align__(16) __half g_hs1h[(size_t)N_NODES * 128];  // layer-1 gather rows (fp16)
__device__ __align__(16) __half g_hs2h[(size_t)N_NODES * 128];  // layer-2 gather rows (fp16)

// ---------------- PTX helpers ---------------------------------------------------
__device__ __forceinline__ uint32_t smem_u32(const void* p) {
    uint32_t a;
    asm("{ .reg .u64 t; cvta.to.shared.u64 t, %1; cvt.u32.u64 %0, t; }" : "=r"(a) : "l"(p));
    return a;
}
#define CP16(dst, src) \
    asm volatile("cp.async.cg.shared.global [%0], [%1], 16;" :: "r"(dst), "l"(src))
#define CP_COMMIT() asm volatile("cp.async.commit_group;")
#define CP_WAIT1()  asm volatile("cp.async.wait_group 1;")
#define CP_WAIT0()  asm volatile("cp.async.wait_group 0;")

__device__ __forceinline__ void ldsm_x4(uint32_t& r0, uint32_t& r1, uint32_t& r2,
                                        uint32_t& r3, uint32_t addr) {
    asm volatile("ldmatrix.sync.aligned.m8n8.x4.shared.b16 {%0,%1,%2,%3}, [%4];"
                 : "=r"(r0), "=r"(r1), "=r"(r2), "=r"(r3) : "r"(addr));
}
__device__ __forceinline__ void ldsm_x4t(uint32_t& r0, uint32_t& r1, uint32_t& r2,
                                         uint32_t& r3, uint32_t addr) {
    asm volatile("ldmatrix.sync.aligned.m8n8.x4.trans.shared.b16 {%0,%1,%2,%3}, [%4];"
                 : "=r"(r0), "=r"(r1), "=r"(r2), "=r"(r3) : "r"(addr));
}
__device__ __forceinline__ void mma16816(float* c, const uint32_t* a, uint32_t b0, uint32_t b1) {
    asm volatile("mma.sync.aligned.m16n8k16.row.col.f32.bf16.bf16.f32 "
                 "{%0,%1,%2,%3}, {%4,%5,%6,%7}, {%8,%9}, {%0,%1,%2,%3};"
                 : "+f"(c[0]), "+f"(c[1]), "+f"(c[2]), "+f"(c[3])
                 : "r"(a[0]), "r"(a[1]), "r"(a[2]), "r"(a[3]), "r"(b0), "r"(b1));
}
__device__ __forceinline__ uint32_t pack_bf(bf16 a, bf16 b) {
    return (uint32_t)__bfloat16_as_ushort(a) | ((uint32_t)__bfloat16_as_ushort(b) << 16);
}
__device__ __forceinline__ float4 ld_row4h(const __half* base, int lane) {
    uint2 u = __ldg(reinterpret_cast<const uint2*>(base) + lane);
    __half2 h0 = *reinterpret_cast<__half2*>(&u.x);
    __half2 h1 = *reinterpret_cast<__half2*>(&u.y);
    float2 f0 = __half22float2(h0), f1 = __half22float2(h1);
    return make_float4(f0.x, f0.y, f1.x, f1.y);
}

// ---------------- prep: zero hist + weight hi/lo splits ---------------------------
__global__ void prep_kernel(const float* __restrict__ W1,
                            const float* __restrict__ Wmu, const float* __restrict__ Wlv,
                            int N) {
    int i = blockIdx.x * blockDim.x + threadIdx.x;
    if (i < N) g_hist[i] = 0;
    if (i < 256 * 128) {
        float w = W1[i];
        bf16 hi = __float2bfloat16(w);
        g_w1s[i] = hi;
        g_w1s[256 * 128 + i] = __float2bfloat16(w - __bfloat162float(hi));
    }
    if (i < 128 * 128) {
        int k = i >> 7, n = i & 127;
        float w = (n < 64) ? Wmu[k * 64 + n] : Wlv[k * 64 + (n - 64)];
        bf16 hi = __float2bfloat16(w);
        g_w2s[i] = hi;
        g_w2s[128 * 128 + i] = __float2bfloat16(w - __bfloat162float(hi));
    }
}

__global__ void hist_kernel(const int* __restrict__ dst, int E) {
    int e = blockIdx.x * blockDim.x + threadIdx.x;
    if (e < E) atomicAdd(&g_hist[dst[e]], 1);
}

// ---------------- scan (with deginv fused into pass A) ---------------------------
__device__ __forceinline__ int block_exscan(int v, int tid, int* total) {
    __shared__ int wsum[8];
    int lane = tid & 31, w = tid >> 5;
    int x = v;
#pragma unroll
    for (int o = 1; o < 32; o <<= 1) {
        int t = __shfl_up_sync(0xFFFFFFFFu, x, o);
        if (lane >= o) x += t;
    }
    if (lane == 31) wsum[w] = x;
    __syncthreads();
    if (w == 0) {
        int s = (lane < 8) ? wsum[lane] : 0;
#pragma unroll
        for (int o = 1; o < 8; o <<= 1) {
            int t = __shfl_up_sync(0xFFFFFFFFu, s, o);
            if (lane >= o) s += t;
        }
        if (lane < 8) wsum[lane] = s;
    }
    __syncthreads();
    int woff = (w == 0) ? 0 : wsum[w - 1];
    *total = wsum[7];
    return woff + x - v;
}

__global__ void scanA_kernel(int n) {
    int i = blockIdx.x * SCAN_B + threadIdx.x;
    int v = (i < n) ? g_hist[i] : 0;
    if (i < n) g_deginv[i] = rsqrtf(1.0f + (float)v);
    int tot;
    int ex = block_exscan(v, threadIdx.x, &tot);
    if (i < n) g_off[i] = ex;
    if (threadIdx.x == 0) g_bsums[blockIdx.x] = tot;
}
__global__ void scanB_kernel(int nb) {
    int tid = threadIdx.x;
    int v = (tid < nb) ? g_bsums[tid] : 0;
    int tot;
    int ex = block_exscan(v, tid, &tot);
    if (tid < nb) g_bsums[tid] = ex;
}
__global__ void scanC_kernel(int n, int E) {
    int i = blockIdx.x * SCAN_B + threadIdx.x;
    if (i < n) {
        int o = g_off[i] + g_bsums[blockIdx.x];
        g_off[i] = o;
        g_cursor[i] = o;
    }
    if (i == 0) g_off[n] = E;
}
__global__ void place_kernel(const int* __restrict__ src, const int* __restrict__ dst, int E) {
    int e = blockIdx.x * blockDim.x + threadIdx.x;
    if (e >= E) return;
    int pos = atomicAdd(&g_cursor[dst[e]], 1);
    g_esrc[pos] = src[e];
}

// ---------------- GEMM1: hs1 = (x@W1)*deginv[row], fused fp32->bf16 split --------
// Block 128x128, BK=32, 8 warps (4m x 2n), warp tile 32x64.
// A: LDG fp32 x, convert to hi/lo bf16 in regs, STS. B: cp.async bf16 hi/lo tiles.
// Per K-chunk: 3 products (Ah*Bh + Ah*Bl + Al*Bh) into one accumulator.
#define A_PITCH 40
#define B_PITCH 136
#define A_BUF   (128 * A_PITCH * 2)        // bytes per buffer
#define B_BUF   (32 * B_PITCH * 2)
#define SM1_AH  0
#define SM1_AL  (SM1_AH + 2 * A_BUF)
#define SM1_BH  (SM1_AL + 2 * A_BUF)
#define SM1_BL  (SM1_BH + 2 * B_BUF)
#define SM1_BYTES (SM1_BL + 2 * B_BUF)     // 75776

__global__ void __launch_bounds__(256)
mma_gemm1_kernel(const float* __restrict__ x, __half* __restrict__ hs1, int M) {
    extern __shared__ __align__(16) uint8_t smem[];
    const uint32_t sbase = smem_u32(smem);
    const int tid = threadIdx.x;
    const int lane = tid & 31, wid = tid >> 5;
    const int warp_m = wid & 3, warp_n = wid >> 2;
    const int block_row = blockIdx.x * 128;

    // A load map: thread -> row tid>>1, 16-col half (tid&1)
    const int arow = tid >> 1, acol = (tid & 1) * 16;
    const int grow = min(block_row + arow, M - 1);
    const float* ap = x + (size_t)grow * 256 + acol;
    const uint32_t a_sts_h = sbase + SM1_AH + (arow * A_PITCH + acol) * 2;
    const uint32_t a_sts_l = sbase + SM1_AL + (arow * A_PITCH + acol) * 2;

    // B load map: rows {bk, bk+16}, seg of 8 bf16
    const int bk = tid >> 4, bseg = tid & 15;
    const uint32_t b_sts_h0 = sbase + SM1_BH + (bk * B_PITCH + bseg * 8) * 2;
    const uint32_t b_sts_h1 = sbase + SM1_BH + ((bk + 16) * B_PITCH + bseg * 8) * 2;
    const uint32_t b_sts_l0 = sbase + SM1_BL + (bk * B_PITCH + bseg * 8) * 2;
    const uint32_t b_sts_l1 = sbase + SM1_BL + ((bk + 16) * B_PITCH + bseg * 8) * 2;
    const bf16* w1h = g_w1s;
    const bf16* w1l = g_w1s + 256 * 128;

    float c[2][8][4];
#pragma unroll
    for (int i = 0; i < 2; i++)
#pragma unroll
        for (int j = 0; j < 8; j++)
#pragma unroll
            for (int q = 0; q < 4; q++) c[i][j][q] = 0.0f;

    float4 areg[4];
#define LDG_A(k0) do { \
        areg[0] = *reinterpret_cast<const float4*>(ap + (k0)); \
        areg[1] = *reinterpret_cast<const float4*>(ap + (k0) + 4); \
        areg[2] = *reinterpret_cast<const float4*>(ap + (k0) + 8); \
        areg[3] = *reinterpret_cast<const float4*>(ap + (k0) + 12); \
    } while (0)
#define STS_A(buf) do { \
        uint4 uh, ul; uint32_t* ph = &uh.x; uint32_t* pl = &ul.x; \
        _Pragma("unroll") \
        for (int q2 = 0; q2 < 2; q2++) { \
            _Pragma("unroll") \
            for (int q = 0; q < 2; q++) { \
                float4 f = areg[q2 * 2 + q]; \
                bf16 h0 = __float2bfloat16(f.x), h1 = __float2bfloat16(f.y); \
                bf16 h2 = __float2bfloat16(f.z), h3 = __float2bfloat16(f.w); \
                bf16 l0 = __float2bfloat16(f.x - __bfloat162float(h0)); \
                bf16 l1 = __float2bfloat16(f.y - __bfloat162float(h1)); \
                bf16 l2 = __float2bfloat16(f.z - __bfloat162float(h2)); \
                bf16 l3 = __float2bfloat16(f.w - __bfloat162float(h3)); \
                ph[q * 2 + 0] = pack_bf(h0, h1); ph[q * 2 + 1] = pack_bf(h2, h3); \
                pl[q * 2 + 0] = pack_bf(l0, l1); pl[q * 2 + 1] = pack_bf(l2, l3); \
            } \
            *reinterpret_cast<uint4*>( \
                (uint8_t*)smem + (a_sts_h - sbase) + (buf) * A_BUF + q2 * 16) = uh; \
            *reinterpret_cast<uint4*>( \
                (uint8_t*)smem + (a_sts_l - sbase) + (buf) * A_BUF + q2 * 16) = ul; \
        } \
    } while (0)
#define CP_B(k0, buf) do { \
        CP16(b_sts_h0 + (buf) * B_BUF, w1h + (size_t)((k0) + bk) * 128 + bseg * 8); \
        CP16(b_sts_h1 + (buf) * B_BUF, w1h + (size_t)((k0) + bk + 16) * 128 + bseg * 8); \
        CP16(b_sts_l0 + (buf) * B_BUF, w1l + (size_t)((k0) + bk) * 128 + bseg * 8); \
        CP16(b_sts_l1 + (buf) * B_BUF, w1l + (size_t)((k0) + bk + 16) * 128 + bseg * 8); \
        CP_COMMIT(); \
    } while (0)

    // prologue: chunk 0
    LDG_A(0);
    CP_B(0, 0);
    STS_A(0);

    const int NT = 256 / 32;  // 8 chunks
#pragma unroll 1
    for (int t = 0; t < NT; t++) {
        const int p = t & 1;
        if (t + 1 < NT) {
            LDG_A((t + 1) * 32);
            CP_B((t + 1) * 32, p ^ 1);
            CP_WAIT1();
        } else {
            CP_WAIT0();
        }
        __syncthreads();
        if (t + 1 < NT) STS_A(p ^ 1);

        const uint32_t ah_b = sbase + SM1_AH + p * A_BUF;
        const uint32_t al_b = sbase + SM1_AL + p * A_BUF;
        const uint32_t bh_b = sbase + SM1_BH + p * B_BUF;
        const uint32_t bl_b = sbase + SM1_BL + p * B_BUF;
#pragma unroll
        for (int ks = 0; ks < 2; ks++) {
            uint32_t ah[2][4], al[2][4], bh[4][4], bl[4][4];
#pragma unroll
            for (int mt = 0; mt < 2; mt++) {
                int row = warp_m * 32 + mt * 16 + (lane & 15);
                int col = ks * 16 + (lane >> 4) * 8;
                ldsm_x4(ah[mt][0], ah[mt][1], ah[mt][2], ah[mt][3],
                        ah_b + (row * A_PITCH + col) * 2);
                ldsm_x4(al[mt][0], al[mt][1], al[mt][2], al[mt][3],
                        al_b + (row * A_PITCH + col) * 2);
            }
#pragma unroll
            for (int np = 0; np < 4; np++) {
                int row = ks * 16 + (lane & 7) + ((lane >> 3) & 1) * 8;
                int col = warp_n * 64 + np * 16 + (lane >> 4) * 8;
                ldsm_x4t(bh[np][0], bh[np][1], bh[np][2], bh[np][3],
                         bh_b + (row * B_PITCH + col) * 2);
                ldsm_x4t(bl[np][0], bl[np][1], bl[np][2], bl[np][3],
                         bl_b + (row * B_PITCH + col) * 2);
            }
#pragma unroll
            for (int mt = 0; mt < 2; mt++)
#pragma unroll
                for (int nt = 0; nt < 8; nt++) {
                    uint32_t b0 = bh[nt >> 1][(nt & 1) * 2], b1 = bh[nt >> 1][(nt & 1) * 2 + 1];
                    uint32_t d0 = bl[nt >> 1][(nt & 1) * 2], d1 = bl[nt >> 1][(nt & 1) * 2 + 1];
                    mma16816(c[mt][nt], ah[mt], b0, b1);
                    mma16816(c[mt][nt], ah[mt], d0, d1);
                    mma16816(c[mt][nt], al[mt], b0, b1);
                }
        }
        __syncthreads();
    }
#undef LDG_A
#undef STS_A
#undef CP_B

    // epilogue: scale by deginv[row], write fp16 rows
#pragma unroll
    for (int mt = 0; mt < 2; mt++) {
        int row0 = block_row + warp_m * 32 + mt * 16 + (lane >> 2);
        int row1 = row0 + 8;
        float s0 = (row0 < M) ? __ldg(&g_deginv[row0]) : 0.0f;
        float s1 = (row1 < M) ? __ldg(&g_deginv[row1]) : 0.0f;
#pragma unroll
        for (int nt = 0; nt < 8; nt++) {
            int col = warp_n * 64 + nt * 8 + (lane & 3) * 2;
            if (row0 < M)
                *reinterpret_cast<__half2*>(hs1 + (size_t)row0 * 128 + col) =
                    __floats2half2_rn(c[mt][nt][0] * s0, c[mt][nt][1] * s0);
            if (row1 < M)
                *reinterpret_cast<__half2*>(hs1 + (size_t)row1 * 128 + col) =
                    __floats2half2_rn(c[mt][nt][2] * s1, c[mt][nt][3] * s1);
        }
    }
}

// ---------------- GEMM2 (bf16 split, from g_h2s) ---------------------------------
struct Smem2 {
    bf16 As[2][128 * A_PITCH];
    bf16 Bs[2][32 * B_PITCH];
};
__global__ void __launch_bounds__(256)
mma_gemm2_kernel(const float* __restrict__ bmu, const float* __restrict__ blv,
                 float* __restrict__ out, int M) {
    __shared__ Smem2 sm;
    const int tid = threadIdx.x;
    const int lane = tid & 31, wid = tid >> 5;
    const int warp_m = wid & 3, warp_n = wid >> 2;
    const int block_row = blockIdx.x * 128;

    const int ar = tid >> 2, aseg = tid & 3;
    const int bk = tid >> 4, bseg = tid & 15;
    const int g0 = min(block_row + ar, M - 1);
    const int g1 = min(block_row + ar + 64, M - 1);
    const bf16* ap0 = g_h2s + (size_t)g0 * 256 + aseg * 8;
    const bf16* ap1 = g_h2s + (size_t)g1 * 256 + aseg * 8;
    const uint32_t asm0 = smem_u32(&sm.As[0][ar * A_PITCH + aseg * 8]);
    const uint32_t asm1 = smem_u32(&sm.As[0][(ar + 64) * A_PITCH + aseg * 8]);
    const uint32_t bsm0 = smem_u32(&sm.Bs[0][bk * B_PITCH + bseg * 8]);
    const uint32_t bsm1 = smem_u32(&sm.Bs[0][(bk + 16) * B_PITCH + bseg * 8]);
    const uint32_t a_ld0 = smem_u32(&sm.As[0][0]);
    const uint32_t b_ld0 = smem_u32(&sm.Bs[0][0]);

    float c[2][8][4];
#pragma unroll
    for (int i = 0; i < 2; i++)
#pragma unroll
        for (int j = 0; j < 8; j++)
#pragma unroll
            for (int q = 0; q < 4; q++) c[i][j][q] = 0.0f;

    const int IPP = 128 / 32, NT = 3 * IPP;  // 3 passes: AhBh, AhBl, AlBh
#define ISSUE2(it, buf) do { \
        int _pass = (it) / IPP, _kk = ((it) % IPP) * 32; \
        int _aoff = (_pass == 2) ? 128 : 0; \
        const bf16* _bb = g_w2s + ((_pass == 1) ? (size_t)128 * 128 : 0); \
        CP16(asm0 + (buf) * A_BUF, ap0 + _aoff + _kk); \
        CP16(asm1 + (buf) * A_BUF, ap1 + _aoff + _kk); \
        CP16(bsm0 + (buf) * B_BUF, _bb + (size_t)(_kk + bk) * 128 + bseg * 8); \
        CP16(bsm1 + (buf) * B_BUF, _bb + (size_t)(_kk + bk + 16) * 128 + bseg * 8); \
        CP_COMMIT(); \
    } while (0)

    ISSUE2(0, 0);
#pragma unroll 1
    for (int it = 0; it < NT; it++) {
        const int p = it & 1;
        if (it + 1 < NT) { ISSUE2(it + 1, p ^ 1); CP_WAIT1(); }
        else            { CP_WAIT0(); }
        __syncthreads();
        const uint32_t abase = a_ld0 + p * A_BUF;
        const uint32_t bbase = b_ld0 + p * B_BUF;
#pragma unroll
        for (int ks = 0; ks < 2; ks++) {
            uint32_t a[2][4], b[4][4];
#pragma unroll
            for (int mt = 0; mt < 2; mt++) {
                int row = warp_m * 32 + mt * 16 + (lane & 15);
                int col = ks * 16 + (lane >> 4) * 8;
                ldsm_x4(a[mt][0], a[mt][1], a[mt][2], a[mt][3],
                        abase + (row * A_PITCH + col) * 2);
            }
#pragma unroll
            for (int np = 0; np < 4; np++) {
                int row = ks * 16 + (lane & 7) + ((lane >> 3) & 1) * 8;
                int col = warp_n * 64 + np * 16 + (lane >> 4) * 8;
                ldsm_x4t(b[np][0], b[np][1], b[np][2], b[np][3],
                         bbase + (row * B_PITCH + col) * 2);
            }
#pragma unroll
            for (int mt = 0; mt < 2; mt++)
#pragma unroll
                for (int nt = 0; nt < 8; nt++)
                    mma16816(c[mt][nt], a[mt],
                             b[nt >> 1][(nt & 1) * 2], b[nt >> 1][(nt & 1) * 2 + 1]);
        }
        __syncthreads();
    }
#undef ISSUE2

    const float* bias = warp_n ? blv : bmu;
    float* base = out + (warp_n ? (size_t)M * 64 : 0);
#pragma unroll
    for (int mt = 0; mt < 2; mt++) {
        int row0 = block_row + warp_m * 32 + mt * 16 + (lane >> 2);
        int row1 = row0 + 8;
#pragma unroll
        for (int nt = 0; nt < 8; nt++) {
            int col = nt * 8 + (lane & 3) * 2;
            float b0 = __ldg(&bias[col]), b1 = __ldg(&bias[col + 1]);
            if (row0 < M)
                *reinterpret_cast<float2*>(base + (size_t)row0 * 64 + col) =
                    make_float2(c[mt][nt][0] + b0, c[mt][nt][1] + b1);
            if (row1 < M)
                *reinterpret_cast<float2*>(base + (size_t)row1 * 64 + col) =
                    make_float2(c[mt][nt][2] + b0, c[mt][nt][3] + b1);
        }
    }
}

// --------- agg1: warp/node fp16 gather; bias+leaky+rescale -> hs2 (fp16) ----------
__global__ void __launch_bounds__(256)
agg1_kernel(const __half* __restrict__ hs1, const float* __restrict__ b1,
            __half* __restrict__ hs2, int N) {
    int node = (blockIdx.x * blockDim.x + threadIdx.x) >> 5;
    int lane = threadIdx.x & 31;
    if (node >= N) return;
    int beg = g_off[node], end = g_off[node + 1];
    float4 acc = ld_row4h(hs1 + (size_t)node * 128, lane);
    int j = beg;
    for (; j + 3 < end; j += 4) {
        int s0 = __ldg(&g_esrc[j]),     s1 = __ldg(&g_esrc[j + 1]);
        int s2 = __ldg(&g_esrc[j + 2]), s3 = __ldg(&g_esrc[j + 3]);
        float4 v0 = ld_row4h(hs1 + (size_t)s0 * 128, lane);
        float4 v1 = ld_row4h(hs1 + (size_t)s1 * 128, lane);
        float4 v2 = ld_row4h(hs1 + (size_t)s2 * 128, lane);
        float4 v3 = ld_row4h(hs1 + (size_t)s3 * 128, lane);
        acc.x += v0.x + v1.x + v2.x + v3.x;
        acc.y += v0.y + v1.y + v2.y + v3.y;
        acc.z += v0.z + v1.z + v2.z + v3.z;
        acc.w += v0.w + v1.w + v2.w + v3.w;
    }
    for (; j < end; j++) {
        int s = __ldg(&g_esrc[j]);
        float4 v = ld_row4h(hs1 + (size_t)s * 128, lane);
        acc.x += v.x; acc.y += v.y; acc.z += v.z; acc.w += v.w;
    }
    float di = __ldg(&g_deginv[node]);
    float4 b = __ldg(reinterpret_cast<const float4*>(b1) + lane);
    float4 v;
    v.x = acc.x * di + b.x; v.y = acc.y * di + b.y;
    v.z = acc.z * di + b.z; v.w = acc.w * di + b.w;
    v.x = (v.x > 0.f) ? v.x : v.x * NEG_SLOPE;
    v.y = (v.y > 0.f) ? v.y : v.y * NEG_SLOPE;
    v.z = (v.z > 0.f) ? v.z : v.z * NEG_SLOPE;
    v.w = (v.w > 0.f) ? v.w : v.w * NEG_SLOPE;
    uint2 o;
    *reinterpret_cast<__half2*>(&o.x) = __floats2half2_rn(v.x * di, v.y * di);
    *reinterpret_cast<__half2*>(&o.y) = __floats2half2_rn(v.z * di, v.w * di);
    reinterpret_cast<uint2*>(hs2 + (size_t)node * 128)[lane] = o;
}

// --------- agg2: warp/node fp16 gather; scale + bf16 hi/lo split -> g_h2s ---------
__global__ void __launch_bounds__(256)
agg2_kernel(const __half* __restrict__ hs2, int N) {
    int node = (blockIdx.x * blockDim.x + threadIdx.x) >> 5;
    int lane = threadIdx.x & 31;
    if (node >= N) return;
    int beg = g_off[node], end = g_off[node + 1];
    float4 acc = ld_row4h(hs2 + (size_t)node * 128, lane);
    int j = beg;
    for (; j + 3 < end; j += 4) {
        int s0 = __ldg(&g_esrc[j]),     s1 = __ldg(&g_esrc[j + 1]);
        int s2 = __ldg(&g_esrc[j + 2]), s3 = __ldg(&g_esrc[j + 3]);
        float4 v0 = ld_row4h(hs2 + (size_t)s0 * 128, lane);
        float4 v1 = ld_row4h(hs2 + (size_t)s1 * 128, lane);
        float4 v2 = ld_row4h(hs2 + (size_t)s2 * 128, lane);
        float4 v3 = ld_row4h(hs2 + (size_t)s3 * 128, lane);
        acc.x += v0.x + v1.x + v2.x + v3.x;
        acc.y += v0.y + v1.y + v2.y + v3.y;
        acc.z += v0.z + v1.z + v2.z + v3.z;
        acc.w += v0.w + v1.w + v2.w + v3.w;
    }
    for (; j < end; j++) {
        int s = __ldg(&g_esrc[j]);
        float4 v = ld_row4h(hs2 + (size_t)s * 128, lane);
        acc.x += v.x; acc.y += v.y; acc.z += v.z; acc.w += v.w;
    }
    float di = __ldg(&g_deginv[node]);
    float4 w = make_float4(acc.x * di, acc.y * di, acc.z * di, acc.w * di);
    bf16 h0 = __float2bfloat16(w.x), h1 = __float2bfloat16(w.y);
    bf16 h2 = __float2bfloat16(w.z), h3 = __float2bfloat16(w.w);
    uint2 hiw, low;
    hiw.x = pack_bf(h0, h1); hiw.y = pack_bf(h2, h3);
    low.x = pack_bf(__float2bfloat16(w.x - __bfloat162float(h0)),
                    __float2bfloat16(w.y - __bfloat162float(h1)));
    low.y = pack_bf(__float2bfloat16(w.z - __bfloat162float(h2)),
                    __float2bfloat16(w.w - __bfloat162float(h3)));
    bf16* o = g_h2s + (size_t)node * 256;
    reinterpret_cast<uint2*>(o)[lane] = hiw;
    reinterpret_cast<uint2*>(o + 128)[lane] = low;
}

// ---------------- launch -----------------------------------------------------------
extern "C" void kernel_launch(void* const* d_in, const int* in_sizes, int n_in,
                              void* d_out, int out_size) {
    const float* x   = (const float*)d_in[0];
    const int*   ei  = (const int*)d_in[1];   // int32 (JAX x64 disabled)
    const float* W1  = (const float*)d_in[2];
    const float* b1  = (const float*)d_in[3];
    const float* Wmu = (const float*)d_in[4];
    const float* bmu = (const float*)d_in[5];
    const float* Wlv = (const float*)d_in[6];
    const float* blv = (const float*)d_in[7];
    float* out = (float*)d_out;

    const int N = in_sizes[0] / F_IN;  // 50000
    const int E = in_sizes[1] / 2;     // 800000
    const int* src = ei;
    const int* dst = ei + E;

    __half *hs1, *hs2;
    cudaGetSymbolAddress((void**)&hs1, g_hs1h);
    cudaGetSymbolAddress((void**)&hs2, g_hs2h);

    cudaFuncSetAttribute(mma_gemm1_kernel,
                         cudaFuncAttributeMaxDynamicSharedMemorySize, SM1_BYTES);

    const int nScanBlocks = (N + SCAN_B - 1) / SCAN_B;

    // 1) prep (zero hist + weight splits) and CSR build
    prep_kernel<<<(N + 255) / 256, 256>>>(W1, Wmu, Wlv, N);
    hist_kernel<<<(E + 255) / 256, 256>>>(dst, E);
    scanA_kernel<<<nScanBlocks, SCAN_B>>>(N);
    scanB_kernel<<<1, SCAN_B>>>(nScanBlocks);
    scanC_kernel<<<nScanBlocks, SCAN_B>>>(N, E);
    place_kernel<<<(E + 255) / 256, 256>>>(src, dst, E);

    // 2) GEMM1 (fused fp32->bf16 split): hs1 = (x@W1)*deginv[row], fp16 rows
    mma_gemm1_kernel<<<(N + 127) / 128, 256, SM1_BYTES>>>(x, hs1, N);

    // 3) agg1 (CSR gather + self + bias + leaky + rescale) -> hs2 fp16
    agg1_kernel<<<(N * 32 + 255) / 256, 256>>>(hs1, b1, hs2, N);

    // 4) agg2 (CSR gather + self + scale + bf16 split) -> g_h2s
    agg2_kernel<<<(N * 32 + 255) / 256, 256>>>(hs2, N);

    // 5) GEMM2 + bias + mu/logvar split
    mma_gemm2_kernel<<<(N + 127) / 128, 256>>>(bmu, blv, out, N);
}

// round 8
// speedup vs baseline: 2.6521x; 1.0334x over previous
#include <cuda_runtime.h>
#include <cuda_bf16.h>
#include <cuda_fp16.h>
#include <stdint.h>

#define N_NODES 50000
#define F_IN    256
#define F_HID   128
#define NEG_SLOPE 0.01f
#define MAXE    800000
#define SCAN_B  256
#define NSCAN   ((N_NODES + SCAN_B - 1) / SCAN_B)

typedef __nv_bfloat16 bf16;

// ---------------- scratch ------------------------------------------------------
__device__ __align__(16) int    g_hist[N_NODES];
__device__ __align__(16) int    g_off[N_NODES + 1];
__device__ __align__(16) int    g_cursor[N_NODES];
__device__ __align__(16) int    g_esrc[MAXE];
__device__ __align__(16) float  g_deginv[N_NODES];
__device__ volatile unsigned long long g_states[NSCAN];
__device__ int    g_ticket;
__device__ __align__(16) bf16   g_w1s[2 * 256 * 128];           // [hi|lo] of W1, [k][n]
__device__ __align__(16) bf16   g_h2s[(size_t)N_NODES * 256];   // agg2 out: [hi|lo]
__device__ __align__(16) bf16   g_w2s[2 * 128 * 128];           // [hi|lo] of [Wmu|Wlv]
__device__ __align__(16) __half g_hs1h[(size_t)N_NODES * 128];  // layer-1 rows (UNscaled)
__device__ __align__(16) __half g_hs2h[(size_t)N_NODES * 128];  // layer-2 rows (pre-scaled)

// ---------------- PTX helpers ---------------------------------------------------
__device__ __forceinline__ uint32_t smem_u32(const void* p) {
    uint32_t a;
    asm("{ .reg .u64 t; cvta.to.shared.u64 t, %1; cvt.u32.u64 %0, t; }" : "=r"(a) : "l"(p));
    return a;
}
#define CP16(dst, src) \
    asm volatile("cp.async.cg.shared.global [%0], [%1], 16;" :: "r"(dst), "l"(src))
#define CP_COMMIT() asm volatile("cp.async.commit_group;")
#define CP_WAIT1()  asm volatile("cp.async.wait_group 1;")
#define CP_WAIT0()  asm volatile("cp.async.wait_group 0;")

__device__ __forceinline__ void ldsm_x4(uint32_t& r0, uint32_t& r1, uint32_t& r2,
                                        uint32_t& r3, uint32_t addr) {
    asm volatile("ldmatrix.sync.aligned.m8n8.x4.shared.b16 {%0,%1,%2,%3}, [%4];"
                 : "=r"(r0), "=r"(r1), "=r"(r2), "=r"(r3) : "r"(addr));
}
__device__ __forceinline__ void ldsm_x4t(uint32_t& r0, uint32_t& r1, uint32_t& r2,
                                         uint32_t& r3, uint32_t addr) {
    asm volatile("ldmatrix.sync.aligned.m8n8.x4.trans.shared.b16 {%0,%1,%2,%3}, [%4];"
                 : "=r"(r0), "=r"(r1), "=r"(r2), "=r"(r3) : "r"(addr));
}
__device__ __forceinline__ void mma16816(float* c, const uint32_t* a, uint32_t b0, uint32_t b1) {
    asm volatile("mma.sync.aligned.m16n8k16.row.col.f32.bf16.bf16.f32 "
                 "{%0,%1,%2,%3}, {%4,%5,%6,%7}, {%8,%9}, {%0,%1,%2,%3};"
                 : "+f"(c[0]), "+f"(c[1]), "+f"(c[2]), "+f"(c[3])
                 : "r"(a[0]), "r"(a[1]), "r"(a[2]), "r"(a[3]), "r"(b0), "r"(b1));
}
__device__ __forceinline__ uint32_t pack_bf(bf16 a, bf16 b) {
    return (uint32_t)__bfloat16_as_ushort(a) | ((uint32_t)__bfloat16_as_ushort(b) << 16);
}
__device__ __forceinline__ float4 ld_row4h(const __half* base, int lane) {
    uint2 u = __ldg(reinterpret_cast<const uint2*>(base) + lane);
    __half2 h0 = *reinterpret_cast<__half2*>(&u.x);
    __half2 h1 = *reinterpret_cast<__half2*>(&u.y);
    float2 f0 = __half22float2(h0), f1 = __half22float2(h1);
    return make_float4(f0.x, f0.y, f1.x, f1.y);
}

// ---------------- stream-A prep: zero CSR state ------------------------------------
__global__ void prep_csr_kernel(int N) {
    int i = blockIdx.x * blockDim.x + threadIdx.x;
    if (i < N) g_hist[i] = 0;
    if (i < NSCAN) g_states[i] = 0ull;
    if (i == 0) g_ticket = 0;
}
// ---------------- stream-B prep: weight hi/lo splits --------------------------------
__global__ void prep_w_kernel(const float* __restrict__ W1,
                              const float* __restrict__ Wmu, const float* __restrict__ Wlv) {
    int i = blockIdx.x * blockDim.x + threadIdx.x;
    if (i < 256 * 128) {
        float w = W1[i];
        bf16 hi = __float2bfloat16(w);
        g_w1s[i] = hi;
        g_w1s[256 * 128 + i] = __float2bfloat16(w - __bfloat162float(hi));
    }
    if (i < 128 * 128) {
        int k = i >> 7, n = i & 127;
        float w = (n < 64) ? Wmu[k * 64 + n] : Wlv[k * 64 + (n - 64)];
        bf16 hi = __float2bfloat16(w);
        g_w2s[i] = hi;
        g_w2s[128 * 128 + i] = __float2bfloat16(w - __bfloat162float(hi));
    }
}

__global__ void hist_kernel(const int* __restrict__ dst, int E) {
    int e = blockIdx.x * blockDim.x + threadIdx.x;
    if (e < E) atomicAdd(&g_hist[dst[e]], 1);
}

// ---------------- single-pass decoupled-lookback scan (+deginv) ---------------------
__device__ __forceinline__ int block_exscan(int v, int tid, int* total) {
    __shared__ int wsum[8];
    int lane = tid & 31, w = tid >> 5;
    int x = v;
#pragma unroll
    for (int o = 1; o < 32; o <<= 1) {
        int t = __shfl_up_sync(0xFFFFFFFFu, x, o);
        if (lane >= o) x += t;
    }
    if (lane == 31) wsum[w] = x;
    __syncthreads();
    if (w == 0) {
        int s = (lane < 8) ? wsum[lane] : 0;
#pragma unroll
        for (int o = 1; o < 8; o <<= 1) {
            int t = __shfl_up_sync(0xFFFFFFFFu, s, o);
            if (lane >= o) s += t;
        }
        if (lane < 8) wsum[lane] = s;
    }
    __syncthreads();
    int woff = (w == 0) ? 0 : wsum[w - 1];
    *total = wsum[7];
    return woff + x - v;
}

__global__ void scan_kernel(int n, int E) {
    __shared__ int sbid;
    __shared__ int srun;
    if (threadIdx.x == 0) sbid = atomicAdd(&g_ticket, 1);
    __syncthreads();
    const int bid = sbid;
    const int i = bid * SCAN_B + threadIdx.x;
    int v = (i < n) ? g_hist[i] : 0;
    if (i < n) g_deginv[i] = rsqrtf(1.0f + (float)v);
    int tot;
    int ex = block_exscan(v, threadIdx.x, &tot);
    if (threadIdx.x == 0) {
        if (bid == 0) {
            g_states[0] = ((unsigned long long)tot << 2) | 2ull;
            srun = 0;
        } else {
            g_states[bid] = ((unsigned long long)tot << 2) | 1ull;
            int run = 0, j = bid - 1;
            while (true) {
                unsigned long long s;
                do { s = g_states[j]; } while ((s & 3ull) == 0ull);
                run += (int)(s >> 2);
                if ((s & 3ull) == 2ull) break;
                j--;
            }
            g_states[bid] = ((unsigned long long)(run + tot) << 2) | 2ull;
            srun = run;
        }
    }
    __syncthreads();
    if (i < n) {
        int o = ex + srun;
        g_off[i] = o;
        g_cursor[i] = o;
    }
    if (i == 0) g_off[n] = E;
}

__global__ void place_kernel(const int* __restrict__ src, const int* __restrict__ dst, int E) {
    int e = blockIdx.x * blockDim.x + threadIdx.x;
    if (e >= E) return;
    int pos = atomicAdd(&g_cursor[dst[e]], 1);
    g_esrc[pos] = src[e];
}

// ---------------- GEMM1: hs1 = x@W1 (UNscaled), fused fp32->bf16 split -------------
#define A_PITCH 40
#define B_PITCH 136
#define A_BUF   (128 * A_PITCH * 2)
#define B_BUF   (32 * B_PITCH * 2)
#define SM1_AH  0
#define SM1_AL  (SM1_AH + 2 * A_BUF)
#define SM1_BH  (SM1_AL + 2 * A_BUF)
#define SM1_BL  (SM1_BH + 2 * B_BUF)
#define SM1_BYTES (SM1_BL + 2 * B_BUF)

__global__ void __launch_bounds__(256)
mma_gemm1_kernel(const float* __restrict__ x, __half* __restrict__ hs1, int M) {
    extern __shared__ __align__(16) uint8_t smem[];
    const uint32_t sbase = smem_u32(smem);
    const int tid = threadIdx.x;
    const int lane = tid & 31, wid = tid >> 5;
    const int warp_m = wid & 3, warp_n = wid >> 2;
    const int block_row = blockIdx.x * 128;

    const int arow = tid >> 1, acol = (tid & 1) * 16;
    const int grow = min(block_row + arow, M - 1);
    const float* ap = x + (size_t)grow * 256 + acol;
    const uint32_t a_sts_h = sbase + SM1_AH + (arow * A_PITCH + acol) * 2;
    const uint32_t a_sts_l = sbase + SM1_AL + (arow * A_PITCH + acol) * 2;

    const int bk = tid >> 4, bseg = tid & 15;
    const uint32_t b_sts_h0 = sbase + SM1_BH + (bk * B_PITCH + bseg * 8) * 2;
    const uint32_t b_sts_h1 = sbase + SM1_BH + ((bk + 16) * B_PITCH + bseg * 8) * 2;
    const uint32_t b_sts_l0 = sbase + SM1_BL + (bk * B_PITCH + bseg * 8) * 2;
    const uint32_t b_sts_l1 = sbase + SM1_BL + ((bk + 16) * B_PITCH + bseg * 8) * 2;
    const bf16* w1h = g_w1s;
    const bf16* w1l = g_w1s + 256 * 128;

    float c[2][8][4];
#pragma unroll
    for (int i = 0; i < 2; i++)
#pragma unroll
        for (int j = 0; j < 8; j++)
#pragma unroll
            for (int q = 0; q < 4; q++) c[i][j][q] = 0.0f;

    float4 areg[4];
#define LDG_A(k0) do { \
        areg[0] = *reinterpret_cast<const float4*>(ap + (k0)); \
        areg[1] = *reinterpret_cast<const float4*>(ap + (k0) + 4); \
        areg[2] = *reinterpret_cast<const float4*>(ap + (k0) + 8); \
        areg[3] = *reinterpret_cast<const float4*>(ap + (k0) + 12); \
    } while (0)
#define STS_A(buf) do { \
        uint4 uh, ul; uint32_t* ph = &uh.x; uint32_t* pl = &ul.x; \
        _Pragma("unroll") \
        for (int q2 = 0; q2 < 2; q2++) { \
            _Pragma("unroll") \
            for (int q = 0; q < 2; q++) { \
                float4 f = areg[q2 * 2 + q]; \
                bf16 h0 = __float2bfloat16(f.x), h1 = __float2bfloat16(f.y); \
                bf16 h2 = __float2bfloat16(f.z), h3 = __float2bfloat16(f.w); \
                bf16 l0 = __float2bfloat16(f.x - __bfloat162float(h0)); \
                bf16 l1 = __float2bfloat16(f.y - __bfloat162float(h1)); \
                bf16 l2 = __float2bfloat16(f.z - __bfloat162float(h2)); \
                bf16 l3 = __float2bfloat16(f.w - __bfloat162float(h3)); \
                ph[q * 2 + 0] = pack_bf(h0, h1); ph[q * 2 + 1] = pack_bf(h2, h3); \
                pl[q * 2 + 0] = pack_bf(l0, l1); pl[q * 2 + 1] = pack_bf(l2, l3); \
            } \
            *reinterpret_cast<uint4*>( \
                (uint8_t*)smem + (a_sts_h - sbase) + (buf) * A_BUF + q2 * 16) = uh; \
            *reinterpret_cast<uint4*>( \
                (uint8_t*)smem + (a_sts_l - sbase) + (buf) * A_BUF + q2 * 16) = ul; \
        } \
    } while (0)
#define CP_B(k0, buf) do { \
        CP16(b_sts_h0 + (buf) * B_BUF, w1h + (size_t)((k0) + bk) * 128 + bseg * 8); \
        CP16(b_sts_h1 + (buf) * B_BUF, w1h + (size_t)((k0) + bk + 16) * 128 + bseg * 8); \
        CP16(b_sts_l0 + (buf) * B_BUF, w1l + (size_t)((k0) + bk) * 128 + bseg * 8); \
        CP16(b_sts_l1 + (buf) * B_BUF, w1l + (size_t)((k0) + bk + 16) * 128 + bseg * 8); \
        CP_COMMIT(); \
    } while (0)

    LDG_A(0);
    CP_B(0, 0);
    STS_A(0);

    const int NT = 256 / 32;
#pragma unroll 1
    for (int t = 0; t < NT; t++) {
        const int p = t & 1;
        if (t + 1 < NT) {
            LDG_A((t + 1) * 32);
            CP_B((t + 1) * 32, p ^ 1);
            CP_WAIT1();
        } else {
            CP_WAIT0();
        }
        __syncthreads();
        if (t + 1 < NT) STS_A(p ^ 1);

        const uint32_t ah_b = sbase + SM1_AH + p * A_BUF;
        const uint32_t al_b = sbase + SM1_AL + p * A_BUF;
        const uint32_t bh_b = sbase + SM1_BH + p * B_BUF;
        const uint32_t bl_b = sbase + SM1_BL + p * B_BUF;
#pragma unroll
        for (int ks = 0; ks < 2; ks++) {
            uint32_t ah[2][4], al[2][4], bh[4][4], bl[4][4];
#pragma unroll
            for (int mt = 0; mt < 2; mt++) {
                int row = warp_m * 32 + mt * 16 + (lane & 15);
                int col = ks * 16 + (lane >> 4) * 8;
                ldsm_x4(ah[mt][0], ah[mt][1], ah[mt][2], ah[mt][3],
                        ah_b + (row * A_PITCH + col) * 2);
                ldsm_x4(al[mt][0], al[mt][1], al[mt][2], al[mt][3],
                        al_b + (row * A_PITCH + col) * 2);
            }
#pragma unroll
            for (int np = 0; np < 4; np++) {
                int row = ks * 16 + (lane & 7) + ((lane >> 3) & 1) * 8;
                int col = warp_n * 64 + np * 16 + (lane >> 4) * 8;
                ldsm_x4t(bh[np][0], bh[np][1], bh[np][2], bh[np][3],
                         bh_b + (row * B_PITCH + col) * 2);
                ldsm_x4t(bl[np][0], bl[np][1], bl[np][2], bl[np][3],
                         bl_b + (row * B_PITCH + col) * 2);
            }
#pragma unroll
            for (int mt = 0; mt < 2; mt++)
#pragma unroll
                for (int nt = 0; nt < 8; nt++) {
                    uint32_t b0 = bh[nt >> 1][(nt & 1) * 2], b1 = bh[nt >> 1][(nt & 1) * 2 + 1];
                    uint32_t d0 = bl[nt >> 1][(nt & 1) * 2], d1 = bl[nt >> 1][(nt & 1) * 2 + 1];
                    mma16816(c[mt][nt], ah[mt], b0, b1);
                    mma16816(c[mt][nt], ah[mt], d0, d1);
                    mma16816(c[mt][nt], al[mt], b0, b1);
                }
        }
        __syncthreads();
    }
#undef LDG_A
#undef STS_A
#undef CP_B

#pragma unroll
    for (int mt = 0; mt < 2; mt++) {
        int row0 = block_row + warp_m * 32 + mt * 16 + (lane >> 2);
        int row1 = row0 + 8;
#pragma unroll
        for (int nt = 0; nt < 8; nt++) {
            int col = warp_n * 64 + nt * 8 + (lane & 3) * 2;
            if (row0 < M)
                *reinterpret_cast<__half2*>(hs1 + (size_t)row0 * 128 + col) =
                    __floats2half2_rn(c[mt][nt][0], c[mt][nt][1]);
            if (row1 < M)
                *reinterpret_cast<__half2*>(hs1 + (size_t)row1 * 128 + col) =
                    __floats2half2_rn(c[mt][nt][2], c[mt][nt][3]);
        }
    }
}

// ---------------- GEMM2 (bf16 split, from g_h2s) -------------------------------------
struct Smem2 {
    bf16 As[2][128 * A_PITCH];
    bf16 Bs[2][32 * B_PITCH];
};
__global__ void __launch_bounds__(256)
mma_gemm2_kernel(const float* __restrict__ bmu, const float* __restrict__ blv,
                 float* __restrict__ out, int M) {
    __shared__ Smem2 sm;
    const int tid = threadIdx.x;
    const int lane = tid & 31, wid = tid >> 5;
    const int warp_m = wid & 3, warp_n = wid >> 2;
    const int block_row = blockIdx.x * 128;

    const int ar = tid >> 2, aseg = tid & 3;
    const int bk = tid >> 4, bseg = tid & 15;
    const int g0 = min(block_row + ar, M - 1);
    const int g1 = min(block_row + ar + 64, M - 1);
    const bf16* ap0 = g_h2s + (size_t)g0 * 256 + aseg * 8;
    const bf16* ap1 = g_h2s + (size_t)g1 * 256 + aseg * 8;
    const uint32_t asm0 = smem_u32(&sm.As[0][ar * A_PITCH + aseg * 8]);
    const uint32_t asm1 = smem_u32(&sm.As[0][(ar + 64) * A_PITCH + aseg * 8]);
    const uint32_t bsm0 = smem_u32(&sm.Bs[0][bk * B_PITCH + bseg * 8]);
    const uint32_t bsm1 = smem_u32(&sm.Bs[0][(bk + 16) * B_PITCH + bseg * 8]);
    const uint32_t a_ld0 = smem_u32(&sm.As[0][0]);
    const uint32_t b_ld0 = smem_u32(&sm.Bs[0][0]);

    float c[2][8][4];
#pragma unroll
    for (int i = 0; i < 2; i++)
#pragma unroll
        for (int j = 0; j < 8; j++)
#pragma unroll
            for (int q = 0; q < 4; q++) c[i][j][q] = 0.0f;

    const int IPP = 128 / 32, NT = 3 * IPP;
#define ISSUE2(it, buf) do { \
        int _pass = (it) / IPP, _kk = ((it) % IPP) * 32; \
        int _aoff = (_pass == 2) ? 128 : 0; \
        const bf16* _bb = g_w2s + ((_pass == 1) ? (size_t)128 * 128 : 0); \
        CP16(asm0 + (buf) * A_BUF, ap0 + _aoff + _kk); \
        CP16(asm1 + (buf) * A_BUF, ap1 + _aoff + _kk); \
        CP16(bsm0 + (buf) * B_BUF, _bb + (size_t)(_kk + bk) * 128 + bseg * 8); \
        CP16(bsm1 + (buf) * B_BUF, _bb + (size_t)(_kk + bk + 16) * 128 + bseg * 8); \
        CP_COMMIT(); \
    } while (0)

    ISSUE2(0, 0);
#pragma unroll 1
    for (int it = 0; it < NT; it++) {
        const int p = it & 1;
        if (it + 1 < NT) { ISSUE2(it + 1, p ^ 1); CP_WAIT1(); }
        else            { CP_WAIT0(); }
        __syncthreads();
        const uint32_t abase = a_ld0 + p * A_BUF;
        const uint32_t bbase = b_ld0 + p * B_BUF;
#pragma unroll
        for (int ks = 0; ks < 2; ks++) {
            uint32_t a[2][4], b[4][4];
#pragma unroll
            for (int mt = 0; mt < 2; mt++) {
                int row = warp_m * 32 + mt * 16 + (lane & 15);
                int col = ks * 16 + (lane >> 4) * 8;
                ldsm_x4(a[mt][0], a[mt][1], a[mt][2], a[mt][3],
                        abase + (row * A_PITCH + col) * 2);
            }
#pragma unroll
            for (int np = 0; np < 4; np++) {
                int row = ks * 16 + (lane & 7) + ((lane >> 3) & 1) * 8;
                int col = warp_n * 64 + np * 16 + (lane >> 4) * 8;
                ldsm_x4t(b[np][0], b[np][1], b[np][2], b[np][3],
                         bbase + (row * B_PITCH + col) * 2);
            }
#pragma unroll
            for (int mt = 0; mt < 2; mt++)
#pragma unroll
                for (int nt = 0; nt < 8; nt++)
                    mma16816(c[mt][nt], a[mt],
                             b[nt >> 1][(nt & 1) * 2], b[nt >> 1][(nt & 1) * 2 + 1]);
        }
        __syncthreads();
    }
#undef ISSUE2

    const float* bias = warp_n ? blv : bmu;
    float* base = out + (warp_n ? (size_t)M * 64 : 0);
#pragma unroll
    for (int mt = 0; mt < 2; mt++) {
        int row0 = block_row + warp_m * 32 + mt * 16 + (lane >> 2);
        int row1 = row0 + 8;
#pragma unroll
        for (int nt = 0; nt < 8; nt++) {
            int col = nt * 8 + (lane & 3) * 2;
            float b0 = __ldg(&bias[col]), b1 = __ldg(&bias[col + 1]);
            if (row0 < M)
                *reinterpret_cast<float2*>(base + (size_t)row0 * 64 + col) =
                    make_float2(c[mt][nt][0] + b0, c[mt][nt][1] + b1);
            if (row1 < M)
                *reinterpret_cast<float2*>(base + (size_t)row1 * 64 + col) =
                    make_float2(c[mt][nt][2] + b0, c[mt][nt][3] + b1);
        }
    }
}

// --------- agg1: warp/node; acc = di*hs1[n] + sum(deginv[s]*hs1[s]);
//           h = leaky(di*acc + b1); hs2 = h*di (pre-scaled) -------------------------
__global__ void __launch_bounds__(256)
agg1_kernel(const __half* __restrict__ hs1, const float* __restrict__ b1,
            __half* __restrict__ hs2, int N) {
    int node = (blockIdx.x * blockDim.x + threadIdx.x) >> 5;
    int lane = threadIdx.x & 31;
    if (node >= N) return;
    int beg = g_off[node], end = g_off[node + 1];
    float di = __ldg(&g_deginv[node]);
    float4 sv = ld_row4h(hs1 + (size_t)node * 128, lane);
    float4 acc = make_float4(sv.x * di, sv.y * di, sv.z * di, sv.w * di);
    int j = beg;
    for (; j + 3 < end; j += 4) {
        int s0 = __ldg(&g_esrc[j]),     s1 = __ldg(&g_esrc[j + 1]);
        int s2 = __ldg(&g_esrc[j + 2]), s3 = __ldg(&g_esrc[j + 3]);
        float d0 = __ldg(&g_deginv[s0]), d1 = __ldg(&g_deginv[s1]);
        float d2 = __ldg(&g_deginv[s2]), d3 = __ldg(&g_deginv[s3]);
        float4 v0 = ld_row4h(hs1 + (size_t)s0 * 128, lane);
        float4 v1 = ld_row4h(hs1 + (size_t)s1 * 128, lane);
        float4 v2 = ld_row4h(hs1 + (size_t)s2 * 128, lane);
        float4 v3 = ld_row4h(hs1 + (size_t)s3 * 128, lane);
        acc.x += v0.x * d0 + v1.x * d1 + v2.x * d2 + v3.x * d3;
        acc.y += v0.y * d0 + v1.y * d1 + v2.y * d2 + v3.y * d3;
        acc.z += v0.z * d0 + v1.z * d1 + v2.z * d2 + v3.z * d3;
        acc.w += v0.w * d0 + v1.w * d1 + v2.w * d2 + v3.w * d3;
    }
    for (; j < end; j++) {
        int s = __ldg(&g_esrc[j]);
        float d = __ldg(&g_deginv[s]);
        float4 v = ld_row4h(hs1 + (size_t)s * 128, lane);
        acc.x += v.x * d; acc.y += v.y * d; acc.z += v.z * d; acc.w += v.w * d;
    }
    float4 b = __ldg(reinterpret_cast<const float4*>(b1) + lane);
    float4 v;
    v.x = acc.x * di + b.x; v.y = acc.y * di + b.y;
    v.z = acc.z * di + b.z; v.w = acc.w * di + b.w;
    v.x = (v.x > 0.f) ? v.x : v.x * NEG_SLOPE;
    v.y = (v.y > 0.f) ? v.y : v.y * NEG_SLOPE;
    v.z = (v.z > 0.f) ? v.z : v.z * NEG_SLOPE;
    v.w = (v.w > 0.f) ? v.w : v.w * NEG_SLOPE;
    uint2 o;
    *reinterpret_cast<__half2*>(&o.x) = __floats2half2_rn(v.x * di, v.y * di);
    *reinterpret_cast<__half2*>(&o.y) = __floats2half2_rn(v.z * di, v.w * di);
    reinterpret_cast<uint2*>(hs2 + (size_t)node * 128)[lane] = o;
}

// --------- agg2: warp/node (hs2 pre-scaled); scale + bf16 hi/lo split ----------------
__global__ void __launch_bounds__(256)
agg2_kernel(const __half* __restrict__ hs2, int N) {
    int node = (blockIdx.x * blockDim.x + threadIdx.x) >> 5;
    int lane = threadIdx.x & 31;
    if (node >= N) return;
    int beg = g_off[node], end = g_off[node + 1];
    float4 acc = ld_row4h(hs2 + (size_t)node * 128, lane);
    int j = beg;
    for (; j + 3 < end; j += 4) {
        int s0 = __ldg(&g_esrc[j]),     s1 = __ldg(&g_esrc[j + 1]);
        int s2 = __ldg(&g_esrc[j + 2]), s3 = __ldg(&g_esrc[j + 3]);
        float4 v0 = ld_row4h(hs2 + (size_t)s0 * 128, lane);
        float4 v1 = ld_row4h(hs2 + (size_t)s1 * 128, lane);
        float4 v2 = ld_row4h(hs2 + (size_t)s2 * 128, lane);
        float4 v3 = ld_row4h(hs2 + (size_t)s3 * 128, lane);
        acc.x += v0.x + v1.x + v2.x + v3.x;
        acc.y += v0.y + v1.y + v2.y + v3.y;
        acc.z += v0.z + v1.z + v2.z + v3.z;
        acc.w += v0.w + v1.w + v2.w + v3.w;
    }
    for (; j < end; j++) {
        int s = __ldg(&g_esrc[j]);
        float4 v = ld_row4h(hs2 + (size_t)s * 128, lane);
        acc.x += v.x; acc.y += v.y; acc.z += v.z; acc.w += v.w;
    }
    float di = __ldg(&g_deginv[node]);
    float4 w = make_float4(acc.x * di, acc.y * di, acc.z * di, acc.w * di);
    bf16 h0 = __float2bfloat16(w.x), h1 = __float2bfloat16(w.y);
    bf16 h2 = __float2bfloat16(w.z), h3 = __float2bfloat16(w.w);
    uint2 hiw, low;
    hiw.x = pack_bf(h0, h1); hiw.y = pack_bf(h2, h3);
    low.x = pack_bf(__float2bfloat16(w.x - __bfloat162float(h0)),
                    __float2bfloat16(w.y - __bfloat162float(h1)));
    low.y = pack_bf(__float2bfloat16(w.z - __bfloat162float(h2)),
                    __float2bfloat16(w.w - __bfloat162float(h3)));
    bf16* o = g_h2s + (size_t)node * 256;
    reinterpret_cast<uint2*>(o)[lane] = hiw;
    reinterpret_cast<uint2*>(o + 128)[lane] = low;
}

// ---------------- launch ---------------------------------------------------------------
extern "C" void kernel_launch(void* const* d_in, const int* in_sizes, int n_in,
                              void* d_out, int out_size) {
    const float* x   = (const float*)d_in[0];
    const int*   ei  = (const int*)d_in[1];   // int32 (JAX x64 disabled)
    const float* W1  = (const float*)d_in[2];
    const float* b1  = (const float*)d_in[3];
    const float* Wmu = (const float*)d_in[4];
    const float* bmu = (const float*)d_in[5];
    const float* Wlv = (const float*)d_in[6];
    const float* blv = (const float*)d_in[7];
    float* out = (float*)d_out;

    const int N = in_sizes[0] / F_IN;  // 50000
    const int E = in_sizes[1] / 2;     // 800000
    const int* src = ei;
    const int* dst = ei + E;

    __half *hs1, *hs2;
    cudaGetSymbolAddress((void**)&hs1, g_hs1h);
    cudaGetSymbolAddress((void**)&hs2, g_hs2h);

    cudaFuncSetAttribute(mma_gemm1_kernel,
                         cudaFuncAttributeMaxDynamicSharedMemorySize, SM1_BYTES);

    // one-time stream/event creation (host-side resources; reused every call)
    static cudaStream_t sB = nullptr;
    static cudaEvent_t evFork = nullptr, evJoin = nullptr;
    if (sB == nullptr) {
        cudaStreamCreateWithFlags(&sB, cudaStreamNonBlocking);
        cudaEventCreateWithFlags(&evFork, cudaEventDisableTiming);
        cudaEventCreateWithFlags(&evJoin, cudaEventDisableTiming);
    }

    // fork: stream B = GEMM1 path (independent of graph structure)
    cudaEventRecord(evFork, 0);
    cudaStreamWaitEvent(sB, evFork, 0);
    prep_w_kernel<<<(256 * 128 + 255) / 256, 256, 0, sB>>>(W1, Wmu, Wlv);
    mma_gemm1_kernel<<<(N + 127) / 128, 256, SM1_BYTES, sB>>>(x, hs1, N);
    cudaEventRecord(evJoin, sB);

    // stream A (default): CSR build
    prep_csr_kernel<<<(N + 255) / 256, 256>>>(N);
    hist_kernel<<<(E + 255) / 256, 256>>>(dst, E);
    scan_kernel<<<NSCAN, SCAN_B>>>(N, E);
    place_kernel<<<(E + 255) / 256, 256>>>(src, dst, E);

    // join, then the dependent chain
    cudaStreamWaitEvent(0, evJoin, 0);
    agg1_kernel<<<(N * 32 + 255) / 256, 256>>>(hs1, b1, hs2, N);
    agg2_kernel<<<(N * 32 + 255) / 256, 256>>>(hs2, N);
    mma_gemm2_kernel<<<(N + 127) / 128, 256>>>(bmu, blv, out, N);
}

// round 9
// speedup vs baseline: 2.7222x; 1.0264x over previous
#include <cuda_runtime.h>
#include <cuda_bf16.h>
#include <cuda_fp16.h>
#include <stdint.h>

#define N_NODES 50000
#define F_IN    256
#define F_HID   128
#define NEG_SLOPE 0.01f
#define MAXE    800000
#define SCAN_B  256
#define NSCAN   ((N_NODES + SCAN_B - 1) / SCAN_B)

typedef __nv_bfloat16 bf16;

// ---------------- scratch ------------------------------------------------------
__device__ __align__(16) int    g_hist[N_NODES];
__device__ __align__(16) int    g_off[N_NODES + 1];
__device__ __align__(16) int    g_cursor[N_NODES];
__device__ __align__(16) int2   g_epack[MAXE];     // (src, bitcast(deginv[src]))
__device__ __align__(16) float  g_deginv[N_NODES];
__device__ volatile unsigned long long g_states[NSCAN];
__device__ int    g_ticket;
__device__ __align__(16) bf16   g_w1s[2 * 256 * 128];           // [hi|lo] of W1, [k][n]
__device__ __align__(16) bf16   g_h2s[(size_t)N_NODES * 256];   // agg2 out: [hi|lo]
__device__ __align__(16) bf16   g_w2s[2 * 128 * 128];           // [hi|lo] of [Wmu|Wlv]
__device__ __align__(16) __half g_hs1h[(size_t)N_NODES * 128];  // layer-1 rows (UNscaled)
__device__ __align__(16) __half g_hs2h[(size_t)N_NODES * 128];  // layer-2 rows (pre-scaled)

// ---------------- PTX helpers ---------------------------------------------------
__device__ __forceinline__ uint32_t smem_u32(const void* p) {
    uint32_t a;
    asm("{ .reg .u64 t; cvta.to.shared.u64 t, %1; cvt.u32.u64 %0, t; }" : "=r"(a) : "l"(p));
    return a;
}
#define CP16(dst, src) \
    asm volatile("cp.async.cg.shared.global [%0], [%1], 16;" :: "r"(dst), "l"(src))
#define CP_COMMIT() asm volatile("cp.async.commit_group;")
#define CP_WAIT1()  asm volatile("cp.async.wait_group 1;")
#define CP_WAIT0()  asm volatile("cp.async.wait_group 0;")

__device__ __forceinline__ void ldsm_x4(uint32_t& r0, uint32_t& r1, uint32_t& r2,
                                        uint32_t& r3, uint32_t addr) {
    asm volatile("ldmatrix.sync.aligned.m8n8.x4.shared.b16 {%0,%1,%2,%3}, [%4];"
                 : "=r"(r0), "=r"(r1), "=r"(r2), "=r"(r3) : "r"(addr));
}
__device__ __forceinline__ void ldsm_x4t(uint32_t& r0, uint32_t& r1, uint32_t& r2,
                                         uint32_t& r3, uint32_t addr) {
    asm volatile("ldmatrix.sync.aligned.m8n8.x4.trans.shared.b16 {%0,%1,%2,%3}, [%4];"
                 : "=r"(r0), "=r"(r1), "=r"(r2), "=r"(r3) : "r"(addr));
}
__device__ __forceinline__ void mma16816(float* c, const uint32_t* a, uint32_t b0, uint32_t b1) {
    asm volatile("mma.sync.aligned.m16n8k16.row.col.f32.bf16.bf16.f32 "
                 "{%0,%1,%2,%3}, {%4,%5,%6,%7}, {%8,%9}, {%0,%1,%2,%3};"
                 : "+f"(c[0]), "+f"(c[1]), "+f"(c[2]), "+f"(c[3])
                 : "r"(a[0]), "r"(a[1]), "r"(a[2]), "r"(a[3]), "r"(b0), "r"(b1));
}
__device__ __forceinline__ uint32_t pack_bf(bf16 a, bf16 b) {
    return (uint32_t)__bfloat16_as_ushort(a) | ((uint32_t)__bfloat16_as_ushort(b) << 16);
}
__device__ __forceinline__ float4 ld_row4h(const __half* base, int lane) {
    uint2 u = __ldg(reinterpret_cast<const uint2*>(base) + lane);
    __half2 h0 = *reinterpret_cast<__half2*>(&u.x);
    __half2 h1 = *reinterpret_cast<__half2*>(&u.y);
    float2 f0 = __half22float2(h0), f1 = __half22float2(h1);
    return make_float4(f0.x, f0.y, f1.x, f1.y);
}

// ---------------- stream-B prep: weight hi/lo splits --------------------------------
__global__ void prep_w_kernel(const float* __restrict__ W1,
                              const float* __restrict__ Wmu, const float* __restrict__ Wlv) {
    int i = blockIdx.x * blockDim.x + threadIdx.x;
    if (i < 256 * 128) {
        float w = W1[i];
        bf16 hi = __float2bfloat16(w);
        g_w1s[i] = hi;
        g_w1s[256 * 128 + i] = __float2bfloat16(w - __bfloat162float(hi));
    }
    if (i < 128 * 128) {
        int k = i >> 7, n = i & 127;
        float w = (n < 64) ? Wmu[k * 64 + n] : Wlv[k * 64 + (n - 64)];
        bf16 hi = __float2bfloat16(w);
        g_w2s[i] = hi;
        g_w2s[128 * 128 + i] = __float2bfloat16(w - __bfloat162float(hi));
    }
}

// hist: requires g_hist zeroed on entry. Device globals are zero-initialized at
// module load (first call), and place_kernel re-zeroes them at the end of every
// call -> invariant holds for every graph replay.
__global__ void hist_kernel(const int* __restrict__ dst, int E) {
    int e = blockIdx.x * blockDim.x + threadIdx.x;
    if (e < E) atomicAdd(&g_hist[dst[e]], 1);
}

// ---------------- single-pass decoupled-lookback scan (+deginv) ---------------------
__device__ __forceinline__ int block_exscan(int v, int tid, int* total) {
    __shared__ int wsum[8];
    int lane = tid & 31, w = tid >> 5;
    int x = v;
#pragma unroll
    for (int o = 1; o < 32; o <<= 1) {
        int t = __shfl_up_sync(0xFFFFFFFFu, x, o);
        if (lane >= o) x += t;
    }
    if (lane == 31) wsum[w] = x;
    __syncthreads();
    if (w == 0) {
        int s = (lane < 8) ? wsum[lane] : 0;
#pragma unroll
        for (int o = 1; o < 8; o <<= 1) {
            int t = __shfl_up_sync(0xFFFFFFFFu, s, o);
            if (lane >= o) s += t;
        }
        if (lane < 8) wsum[lane] = s;
    }
    __syncthreads();
    int woff = (w == 0) ? 0 : wsum[w - 1];
    *total = wsum[7];
    return woff + x - v;
}

__global__ void scan_kernel(int n, int E) {
    __shared__ int sbid;
    __shared__ int srun;
    if (threadIdx.x == 0) sbid = atomicAdd(&g_ticket, 1);
    __syncthreads();
    const int bid = sbid;
    const int i = bid * SCAN_B + threadIdx.x;
    int v = (i < n) ? g_hist[i] : 0;
    if (i < n) g_deginv[i] = rsqrtf(1.0f + (float)v);
    int tot;
    int ex = block_exscan(v, threadIdx.x, &tot);
    if (threadIdx.x == 0) {
        if (bid == 0) {
            g_states[0] = ((unsigned long long)tot << 2) | 2ull;
            srun = 0;
        } else {
            g_states[bid] = ((unsigned long long)tot << 2) | 1ull;
            int run = 0, j = bid - 1;
            while (true) {
                unsigned long long s;
                do { s = g_states[j]; } while ((s & 3ull) == 0ull);
                run += (int)(s >> 2);
                if ((s & 3ull) == 2ull) break;
                j--;
            }
            g_states[bid] = ((unsigned long long)(run + tot) << 2) | 2ull;
            srun = run;
        }
    }
    __syncthreads();
    if (i < n) {
        int o = ex + srun;
        g_off[i] = o;
        g_cursor[i] = o;
    }
    if (i == 0) g_off[n] = E;
}

// place: writes packed (src, deginv[src]) records sorted by dst; ALSO recycles
// the CSR-build state (hist/states/ticket) so next replay starts clean.
__global__ void place_kernel(const int* __restrict__ src, const int* __restrict__ dst, int E) {
    int e = blockIdx.x * blockDim.x + threadIdx.x;
    if (e < N_NODES) g_hist[e] = 0;
    if (e < NSCAN) g_states[e] = 0ull;
    if (e == 0) g_ticket = 0;
    if (e >= E) return;
    int s = __ldg(&src[e]);
    float d = __ldg(&g_deginv[s]);
    int pos = atomicAdd(&g_cursor[dst[e]], 1);
    g_epack[pos] = make_int2(s, __float_as_int(d));
}

// ---------------- GEMM1: hs1 = x@W1 (UNscaled), fused fp32->bf16 split -------------
#define A_PITCH 40
#define B_PITCH 136
#define A_BUF   (128 * A_PITCH * 2)
#define B_BUF   (32 * B_PITCH * 2)
#define SM1_AH  0
#define SM1_AL  (SM1_AH + 2 * A_BUF)
#define SM1_BH  (SM1_AL + 2 * A_BUF)
#define SM1_BL  (SM1_BH + 2 * B_BUF)
#define SM1_BYTES (SM1_BL + 2 * B_BUF)

__global__ void __launch_bounds__(256)
mma_gemm1_kernel(const float* __restrict__ x, __half* __restrict__ hs1, int M) {
    extern __shared__ __align__(16) uint8_t smem[];
    const uint32_t sbase = smem_u32(smem);
    const int tid = threadIdx.x;
    const int lane = tid & 31, wid = tid >> 5;
    const int warp_m = wid & 3, warp_n = wid >> 2;
    const int block_row = blockIdx.x * 128;

    const int arow = tid >> 1, acol = (tid & 1) * 16;
    const int grow = min(block_row + arow, M - 1);
    const float* ap = x + (size_t)grow * 256 + acol;
    const uint32_t a_sts_h = sbase + SM1_AH + (arow * A_PITCH + acol) * 2;
    const uint32_t a_sts_l = sbase + SM1_AL + (arow * A_PITCH + acol) * 2;

    const int bk = tid >> 4, bseg = tid & 15;
    const uint32_t b_sts_h0 = sbase + SM1_BH + (bk * B_PITCH + bseg * 8) * 2;
    const uint32_t b_sts_h1 = sbase + SM1_BH + ((bk + 16) * B_PITCH + bseg * 8) * 2;
    const uint32_t b_sts_l0 = sbase + SM1_BL + (bk * B_PITCH + bseg * 8) * 2;
    const uint32_t b_sts_l1 = sbase + SM1_BL + ((bk + 16) * B_PITCH + bseg * 8) * 2;
    const bf16* w1h = g_w1s;
    const bf16* w1l = g_w1s + 256 * 128;

    float c[2][8][4];
#pragma unroll
    for (int i = 0; i < 2; i++)
#pragma unroll
        for (int j = 0; j < 8; j++)
#pragma unroll
            for (int q = 0; q < 4; q++) c[i][j][q] = 0.0f;

    float4 areg[4];
#define LDG_A(k0) do { \
        areg[0] = *reinterpret_cast<const float4*>(ap + (k0)); \
        areg[1] = *reinterpret_cast<const float4*>(ap + (k0) + 4); \
        areg[2] = *reinterpret_cast<const float4*>(ap + (k0) + 8); \
        areg[3] = *reinterpret_cast<const float4*>(ap + (k0) + 12); \
    } while (0)
#define STS_A(buf) do { \
        uint4 uh, ul; uint32_t* ph = &uh.x; uint32_t* pl = &ul.x; \
        _Pragma("unroll") \
        for (int q2 = 0; q2 < 2; q2++) { \
            _Pragma("unroll") \
            for (int q = 0; q < 2; q++) { \
                float4 f = areg[q2 * 2 + q]; \
                bf16 h0 = __float2bfloat16(f.x), h1 = __float2bfloat16(f.y); \
                bf16 h2 = __float2bfloat16(f.z), h3 = __float2bfloat16(f.w); \
                bf16 l0 = __float2bfloat16(f.x - __bfloat162float(h0)); \
                bf16 l1 = __float2bfloat16(f.y - __bfloat162float(h1)); \
                bf16 l2 = __float2bfloat16(f.z - __bfloat162float(h2)); \
                bf16 l3 = __float2bfloat16(f.w - __bfloat162float(h3)); \
                ph[q * 2 + 0] = pack_bf(h0, h1); ph[q * 2 + 1] = pack_bf(h2, h3); \
                pl[q * 2 + 0] = pack_bf(l0, l1); pl[q * 2 + 1] = pack_bf(l2, l3); \
            } \
            *reinterpret_cast<uint4*>( \
                (uint8_t*)smem + (a_sts_h - sbase) + (buf) * A_BUF + q2 * 16) = uh; \
            *reinterpret_cast<uint4*>( \
                (uint8_t*)smem + (a_sts_l - sbase) + (buf) * A_BUF + q2 * 16) = ul; \
        } \
    } while (0)
#define CP_B(k0, buf) do { \
        CP16(b_sts_h0 + (buf) * B_BUF, w1h + (size_t)((k0) + bk) * 128 + bseg * 8); \
        CP16(b_sts_h1 + (buf) * B_BUF, w1h + (size_t)((k0) + bk + 16) * 128 + bseg * 8); \
        CP16(b_sts_l0 + (buf) * B_BUF, w1l + (size_t)((k0) + bk) * 128 + bseg * 8); \
        CP16(b_sts_l1 + (buf) * B_BUF, w1l + (size_t)((k0) + bk + 16) * 128 + bseg * 8); \
        CP_COMMIT(); \
    } while (0)

    LDG_A(0);
    CP_B(0, 0);
    STS_A(0);

    const int NT = 256 / 32;
#pragma unroll 1
    for (int t = 0; t < NT; t++) {
        const int p = t & 1;
        if (t + 1 < NT) {
            LDG_A((t + 1) * 32);
            CP_B((t + 1) * 32, p ^ 1);
            CP_WAIT1();
        } else {
            CP_WAIT0();
        }
        __syncthreads();
        if (t + 1 < NT) STS_A(p ^ 1);

        const uint32_t ah_b = sbase + SM1_AH + p * A_BUF;
        const uint32_t al_b = sbase + SM1_AL + p * A_BUF;
        const uint32_t bh_b = sbase + SM1_BH + p * B_BUF;
        const uint32_t bl_b = sbase + SM1_BL + p * B_BUF;
#pragma unroll
        for (int ks = 0; ks < 2; ks++) {
            uint32_t ah[2][4], al[2][4], bh[4][4], bl[4][4];
#pragma unroll
            for (int mt = 0; mt < 2; mt++) {
                int row = warp_m * 32 + mt * 16 + (lane & 15);
                int col = ks * 16 + (lane >> 4) * 8;
                ldsm_x4(ah[mt][0], ah[mt][1], ah[mt][2], ah[mt][3],
                        ah_b + (row * A_PITCH + col) * 2);
                ldsm_x4(al[mt][0], al[mt][1], al[mt][2], al[mt][3],
                        al_b + (row * A_PITCH + col) * 2);
            }
#pragma unroll
            for (int np = 0; np < 4; np++) {
                int row = ks * 16 + (lane & 7) + ((lane >> 3) & 1) * 8;
                int col = warp_n * 64 + np * 16 + (lane >> 4) * 8;
                ldsm_x4t(bh[np][0], bh[np][1], bh[np][2], bh[np][3],
                         bh_b + (row * B_PITCH + col) * 2);
                ldsm_x4t(bl[np][0], bl[np][1], bl[np][2], bl[np][3],
                         bl_b + (row * B_PITCH + col) * 2);
            }
#pragma unroll
            for (int mt = 0; mt < 2; mt++)
#pragma unroll
                for (int nt = 0; nt < 8; nt++) {
                    uint32_t b0 = bh[nt >> 1][(nt & 1) * 2], b1 = bh[nt >> 1][(nt & 1) * 2 + 1];
                    uint32_t d0 = bl[nt >> 1][(nt & 1) * 2], d1 = bl[nt >> 1][(nt & 1) * 2 + 1];
                    mma16816(c[mt][nt], ah[mt], b0, b1);
                    mma16816(c[mt][nt], ah[mt], d0, d1);
                    mma16816(c[mt][nt], al[mt], b0, b1);
                }
        }
        __syncthreads();
    }
#undef LDG_A
#undef STS_A
#undef CP_B

#pragma unroll
    for (int mt = 0; mt < 2; mt++) {
        int row0 = block_row + warp_m * 32 + mt * 16 + (lane >> 2);
        int row1 = row0 + 8;
#pragma unroll
        for (int nt = 0; nt < 8; nt++) {
            int col = warp_n * 64 + nt * 8 + (lane & 3) * 2;
            if (row0 < M)
                *reinterpret_cast<__half2*>(hs1 + (size_t)row0 * 128 + col) =
                    __floats2half2_rn(c[mt][nt][0], c[mt][nt][1]);
            if (row1 < M)
                *reinterpret_cast<__half2*>(hs1 + (size_t)row1 * 128 + col) =
                    __floats2half2_rn(c[mt][nt][2], c[mt][nt][3]);
        }
    }
}

// ---------------- GEMM2 (bf16 split, from g_h2s) -------------------------------------
struct Smem2 {
    bf16 As[2][128 * A_PITCH];
    bf16 Bs[2][32 * B_PITCH];
};
__global__ void __launch_bounds__(256)
mma_gemm2_kernel(const float* __restrict__ bmu, const float* __restrict__ blv,
                 float* __restrict__ out, int M) {
    __shared__ Smem2 sm;
    const int tid = threadIdx.x;
    const int lane = tid & 31, wid = tid >> 5;
    const int warp_m = wid & 3, warp_n = wid >> 2;
    const int block_row = blockIdx.x * 128;

    const int ar = tid >> 2, aseg = tid & 3;
    const int bk = tid >> 4, bseg = tid & 15;
    const int g0 = min(block_row + ar, M - 1);
    const int g1 = min(block_row + ar + 64, M - 1);
    const bf16* ap0 = g_h2s + (size_t)g0 * 256 + aseg * 8;
    const bf16* ap1 = g_h2s + (size_t)g1 * 256 + aseg * 8;
    const uint32_t asm0 = smem_u32(&sm.As[0][ar * A_PITCH + aseg * 8]);
    const uint32_t asm1 = smem_u32(&sm.As[0][(ar + 64) * A_PITCH + aseg * 8]);
    const uint32_t bsm0 = smem_u32(&sm.Bs[0][bk * B_PITCH + bseg * 8]);
    const uint32_t bsm1 = smem_u32(&sm.Bs[0][(bk + 16) * B_PITCH + bseg * 8]);
    const uint32_t a_ld0 = smem_u32(&sm.As[0][0]);
    const uint32_t b_ld0 = smem_u32(&sm.Bs[0][0]);

    float c[2][8][4];
#pragma unroll
    for (int i = 0; i < 2; i++)
#pragma unroll
        for (int j = 0; j < 8; j++)
#pragma unroll
            for (int q = 0; q < 4; q++) c[i][j][q] = 0.0f;

    const int IPP = 128 / 32, NT = 3 * IPP;
#define ISSUE2(it, buf) do { \
        int _pass = (it) / IPP, _kk = ((it) % IPP) * 32; \
        int _aoff = (_pass == 2) ? 128 : 0; \
        const bf16* _bb = g_w2s + ((_pass == 1) ? (size_t)128 * 128 : 0); \
        CP16(asm0 + (buf) * A_BUF, ap0 + _aoff + _kk); \
        CP16(asm1 + (buf) * A_BUF, ap1 + _aoff + _kk); \
        CP16(bsm0 + (buf) * B_BUF, _bb + (size_t)(_kk + bk) * 128 + bseg * 8); \
        CP16(bsm1 + (buf) * B_BUF, _bb + (size_t)(_kk + bk + 16) * 128 + bseg * 8); \
        CP_COMMIT(); \
    } while (0)

    ISSUE2(0, 0);
#pragma unroll 1
    for (int it = 0; it < NT; it++) {
        const int p = it & 1;
        if (it + 1 < NT) { ISSUE2(it + 1, p ^ 1); CP_WAIT1(); }
        else            { CP_WAIT0(); }
        __syncthreads();
        const uint32_t abase = a_ld0 + p * A_BUF;
        const uint32_t bbase = b_ld0 + p * B_BUF;
#pragma unroll
        for (int ks = 0; ks < 2; ks++) {
            uint32_t a[2][4], b[4][4];
#pragma unroll
            for (int mt = 0; mt < 2; mt++) {
                int row = warp_m * 32 + mt * 16 + (lane & 15);
                int col = ks * 16 + (lane >> 4) * 8;
                ldsm_x4(a[mt][0], a[mt][1], a[mt][2], a[mt][3],
                        abase + (row * A_PITCH + col) * 2);
            }
#pragma unroll
            for (int np = 0; np < 4; np++) {
                int row = ks * 16 + (lane & 7) + ((lane >> 3) & 1) * 8;
                int col = warp_n * 64 + np * 16 + (lane >> 4) * 8;
                ldsm_x4t(b[np][0], b[np][1], b[np][2], b[np][3],
                         bbase + (row * B_PITCH + col) * 2);
            }
#pragma unroll
            for (int mt = 0; mt < 2; mt++)
#pragma unroll
                for (int nt = 0; nt < 8; nt++)
                    mma16816(c[mt][nt], a[mt],
                             b[nt >> 1][(nt & 1) * 2], b[nt >> 1][(nt & 1) * 2 + 1]);
        }
        __syncthreads();
    }
#undef ISSUE2

    const float* bias = warp_n ? blv : bmu;
    float* base = out + (warp_n ? (size_t)M * 64 : 0);
#pragma unroll
    for (int mt = 0; mt < 2; mt++) {
        int row0 = block_row + warp_m * 32 + mt * 16 + (lane >> 2);
        int row1 = row0 + 8;
#pragma unroll
        for (int nt = 0; nt < 8; nt++) {
            int col = nt * 8 + (lane & 3) * 2;
            float b0 = __ldg(&bias[col]), b1 = __ldg(&bias[col + 1]);
            if (row0 < M)
                *reinterpret_cast<float2*>(base + (size_t)row0 * 64 + col) =
                    make_float2(c[mt][nt][0] + b0, c[mt][nt][1] + b1);
            if (row1 < M)
                *reinterpret_cast<float2*>(base + (size_t)row1 * 64 + col) =
                    make_float2(c[mt][nt][2] + b0, c[mt][nt][3] + b1);
        }
    }
}

// --------- agg1: warp/node; acc = di*hs1[n] + sum(d_s*hs1[s]) via packed edges;
//           h = leaky(di*acc + b1); hs2 = h*di (pre-scaled) -------------------------
__global__ void __launch_bounds__(256)
agg1_kernel(const __half* __restrict__ hs1, const float* __restrict__ b1,
            __half* __restrict__ hs2, int N) {
    int node = (blockIdx.x * blockDim.x + threadIdx.x) >> 5;
    int lane = threadIdx.x & 31;
    if (node >= N) return;
    int beg = g_off[node], end = g_off[node + 1];
    float di = __ldg(&g_deginv[node]);
    float4 sv = ld_row4h(hs1 + (size_t)node * 128, lane);
    float4 acc = make_float4(sv.x * di, sv.y * di, sv.z * di, sv.w * di);
    int j = beg;
    for (; j + 7 < end; j += 8) {
        int2 e[8];
        float4 v[8];
#pragma unroll
        for (int k = 0; k < 8; k++) e[k] = __ldg(&g_epack[j + k]);
#pragma unroll
        for (int k = 0; k < 8; k++) v[k] = ld_row4h(hs1 + (size_t)e[k].x * 128, lane);
#pragma unroll
        for (int k = 0; k < 8; k++) {
            float d = __int_as_float(e[k].y);
            acc.x += v[k].x * d; acc.y += v[k].y * d;
            acc.z += v[k].z * d; acc.w += v[k].w * d;
        }
    }
    for (; j < end; j++) {
        int2 e = __ldg(&g_epack[j]);
        float d = __int_as_float(e.y);
        float4 v = ld_row4h(hs1 + (size_t)e.x * 128, lane);
        acc.x += v.x * d; acc.y += v.y * d; acc.z += v.z * d; acc.w += v.w * d;
    }
    float4 b = __ldg(reinterpret_cast<const float4*>(b1) + lane);
    float4 v;
    v.x = acc.x * di + b.x; v.y = acc.y * di + b.y;
    v.z = acc.z * di + b.z; v.w = acc.w * di + b.w;
    v.x = (v.x > 0.f) ? v.x : v.x * NEG_SLOPE;
    v.y = (v.y > 0.f) ? v.y : v.y * NEG_SLOPE;
    v.z = (v.z > 0.f) ? v.z : v.z * NEG_SLOPE;
    v.w = (v.w > 0.f) ? v.w : v.w * NEG_SLOPE;
    uint2 o;
    *reinterpret_cast<__half2*>(&o.x) = __floats2half2_rn(v.x * di, v.y * di);
    *reinterpret_cast<__half2*>(&o.y) = __floats2half2_rn(v.z * di, v.w * di);
    reinterpret_cast<uint2*>(hs2 + (size_t)node * 128)[lane] = o;
}

// --------- agg2: warp/node (hs2 pre-scaled); scale + bf16 hi/lo split ----------------
__global__ void __launch_bounds__(256)
agg2_kernel(const __half* __restrict__ hs2, int N) {
    int node = (blockIdx.x * blockDim.x + threadIdx.x) >> 5;
    int lane = threadIdx.x & 31;
    if (node >= N) return;
    int beg = g_off[node], end = g_off[node + 1];
    float4 acc = ld_row4h(hs2 + (size_t)node * 128, lane);
    int j = beg;
    for (; j + 7 < end; j += 8) {
        int s[8];
        float4 v[8];
#pragma unroll
        for (int k = 0; k < 8; k++) s[k] = __ldg(&g_epack[j + k]).x;
#pragma unroll
        for (int k = 0; k < 8; k++) v[k] = ld_row4h(hs2 + (size_t)s[k] * 128, lane);
#pragma unroll
        for (int k = 0; k < 8; k++) {
            acc.x += v[k].x; acc.y += v[k].y; acc.z += v[k].z; acc.w += v[k].w;
        }
    }
    for (; j < end; j++) {
        int s = __ldg(&g_epack[j]).x;
        float4 v = ld_row4h(hs2 + (size_t)s * 128, lane);
        acc.x += v.x; acc.y += v.y; acc.z += v.z; acc.w += v.w;
    }
    float di = __ldg(&g_deginv[node]);
    float4 w = make_float4(acc.x * di, acc.y * di, acc.z * di, acc.w * di);
    bf16 h0 = __float2bfloat16(w.x), h1 = __float2bfloat16(w.y);
    bf16 h2 = __float2bfloat16(w.z), h3 = __float2bfloat16(w.w);
    uint2 hiw, low;
    hiw.x = pack_bf(h0, h1); hiw.y = pack_bf(h2, h3);
    low.x = pack_bf(__float2bfloat16(w.x - __bfloat162float(h0)),
                    __float2bfloat16(w.y - __bfloat162float(h1)));
    low.y = pack_bf(__float2bfloat16(w.z - __bfloat162float(h2)),
                    __float2bfloat16(w.w - __bfloat162float(h3)));
    bf16* o = g_h2s + (size_t)node * 256;
    reinterpret_cast<uint2*>(o)[lane] = hiw;
    reinterpret_cast<uint2*>(o + 128)[lane] = low;
}

// ---------------- launch ---------------------------------------------------------------
extern "C" void kernel_launch(void* const* d_in, const int* in_sizes, int n_in,
                              void* d_out, int out_size) {
    const float* x   = (const float*)d_in[0];
    const int*   ei  = (const int*)d_in[1];   // int32 (JAX x64 disabled)
    const float* W1  = (const float*)d_in[2];
    const float* b1  = (const float*)d_in[3];
    const float* Wmu = (const float*)d_in[4];
    const float* bmu = (const float*)d_in[5];
    const float* Wlv = (const float*)d_in[6];
    const float* blv = (const float*)d_in[7];
    float* out = (float*)d_out;

    const int N = in_sizes[0] / F_IN;  // 50000
    const int E = in_sizes[1] / 2;     // 800000
    const int* src = ei;
    const int* dst = ei + E;

    __half *hs1, *hs2;
    cudaGetSymbolAddress((void**)&hs1, g_hs1h);
    cudaGetSymbolAddress((void**)&hs2, g_hs2h);

    cudaFuncSetAttribute(mma_gemm1_kernel,
                         cudaFuncAttributeMaxDynamicSharedMemorySize, SM1_BYTES);

    static cudaStream_t sB = nullptr;
    static cudaEvent_t evFork = nullptr, evJoin = nullptr;
    if (sB == nullptr) {
        cudaStreamCreateWithFlags(&sB, cudaStreamNonBlocking);
        cudaEventCreateWithFlags(&evFork, cudaEventDisableTiming);
        cudaEventCreateWithFlags(&evJoin, cudaEventDisableTiming);
    }

    // fork: stream B = GEMM1 path (independent of graph structure)
    cudaEventRecord(evFork, 0);
    cudaStreamWaitEvent(sB, evFork, 0);
    prep_w_kernel<<<(256 * 128 + 255) / 256, 256, 0, sB>>>(W1, Wmu, Wlv);
    mma_gemm1_kernel<<<(N + 127) / 128, 256, SM1_BYTES, sB>>>(x, hs1, N);
    cudaEventRecord(evJoin, sB);

    // stream A (default): CSR build (hist relies on state recycled by previous
    // call's place_kernel; zero-initialized on first call)
    hist_kernel<<<(E + 255) / 256, 256>>>(dst, E);
    scan_kernel<<<NSCAN, SCAN_B>>>(N, E);
    place_kernel<<<(E + 255) / 256, 256>>>(src, dst, E);

    // join, then the dependent chain
    cudaStreamWaitEvent(0, evJoin, 0);
    agg1_kernel<<<(N * 32 + 255) / 256, 256>>>(hs1, b1, hs2, N);
    agg2_kernel<<<(N * 32 + 255) / 256, 256>>>(hs2, N);
    mma_gemm2_kernel<<<(N + 127) / 128, 256>>>(bmu, blv, out, N);
}